// round 15
// baseline (speedup 1.0000x reference)
#include <cuda_runtime.h>
#include <cuda_bf16.h>
#include <math.h>
#include <stdint.h>

// Problem constants
#define Tt 1024
#define Cc 2048
#define Hh 32
#define Nn 64
#define TC (Tt*Cc)          // 2097152
#define SL 32               // scan chunk length
#define NCH (Tt/SL)         // 32 chunks

// tcgen05 available only in architecture-specific compilation passes
#if defined(__CUDA_ARCH_FEAT_SM103_ALL) || defined(__CUDA_ARCH_FEAT_SM100_ALL) || defined(__CUDA_ARCH_SPECIFIC__)
#define HAS_TCGEN05 1
#else
#define HAS_TCGEN05 0
#endif

// ---------------- tcgen05 / mbarrier helpers (sm_103a) ----------------
__device__ __forceinline__ uint32_t smem_u32(const void* p){
  uint32_t a;
  asm("{ .reg .u64 t; cvta.to.shared.u64 t, %1; cvt.u32.u64 %0, t; }" : "=r"(a) : "l"(p));
  return a;
}

#define SW128(x) ((x) ^ (((x) >> 3) & 0x70))

#if HAS_TCGEN05
__device__ __forceinline__ uint32_t elect1(){
  uint32_t r;
  asm volatile("{\n\t.reg .pred p;\n\telect.sync _|p, 0xFFFFFFFF;\n\tselp.b32 %0, 1, 0, p;\n\t}" : "=r"(r));
  return r;
}

#define T5_ALLOC(sa, n)   asm volatile("tcgen05.alloc.cta_group::1.sync.aligned.shared::cta.b32 [%0], %1;" :: "r"(sa), "r"(n) : "memory")
#define T5_DEALLOC(t, n)  asm volatile("tcgen05.dealloc.cta_group::1.sync.aligned.b32 %0, %1;" :: "r"(t), "r"(n))
#define T5_RELINQ()       asm volatile("tcgen05.relinquish_alloc_permit.cta_group::1.sync.aligned;")
#define T5_COMMIT(mb)     asm volatile("tcgen05.commit.cta_group::1.mbarrier::arrive::one.shared::cluster.b64 [%0];" :: "r"(mb) : "memory")
#define T5_FENCE_AFTER()  asm volatile("tcgen05.fence::after_thread_sync;" ::: "memory")
#define T5_WAIT_LD()      asm volatile("tcgen05.wait::ld.sync.aligned;" ::: "memory")
#define FENCE_ASYNC()     asm volatile("fence.proxy.async.shared::cta;" ::: "memory")

#define MBAR_INIT(mb, cnt) asm volatile("mbarrier.init.shared.b64 [%0], %1;" :: "r"(mb), "r"(cnt) : "memory")
#define MBAR_INVAL(mb)     asm volatile("mbarrier.inval.shared.b64 [%0];" :: "r"(mb) : "memory")

#define MBAR_WAIT(mb, ph) do { \
  uint32_t _m = (mb), _p = (ph), _d; \
  asm volatile("{\n\t.reg .pred p;\n\tmbarrier.try_wait.parity.acquire.cta.shared::cta.b64 p, [%1], %2;\n\tselp.b32 %0, 1, 0, p;\n\t}" \
               : "=r"(_d) : "r"(_m), "r"(_p) : "memory"); \
  while (!_d) { \
    asm volatile("{\n\t.reg .pred p;\n\tmbarrier.try_wait.parity.acquire.cta.shared::cta.b64 p, [%1], %2, 0x989680;\n\tselp.b32 %0, 1, 0, p;\n\t}" \
                 : "=r"(_d) : "r"(_m), "r"(_p) : "memory"); \
  } } while(0)

#define LDTM_X32(r, ta) \
    asm volatile( \
        "tcgen05.ld.sync.aligned.32x32b.x32.b32 " \
        "{%0, %1, %2, %3, %4, %5, %6, %7, " \
        " %8, %9, %10, %11, %12, %13, %14, %15, " \
        " %16, %17, %18, %19, %20, %21, %22, %23, " \
        " %24, %25, %26, %27, %28, %29, %30, %31}, [%32];" \
        : "=r"((r)[0]),  "=r"((r)[1]),  "=r"((r)[2]),  "=r"((r)[3]), \
          "=r"((r)[4]),  "=r"((r)[5]),  "=r"((r)[6]),  "=r"((r)[7]), \
          "=r"((r)[8]),  "=r"((r)[9]),  "=r"((r)[10]), "=r"((r)[11]), \
          "=r"((r)[12]), "=r"((r)[13]), "=r"((r)[14]), "=r"((r)[15]), \
          "=r"((r)[16]), "=r"((r)[17]), "=r"((r)[18]), "=r"((r)[19]), \
          "=r"((r)[20]), "=r"((r)[21]), "=r"((r)[22]), "=r"((r)[23]), \
          "=r"((r)[24]), "=r"((r)[25]), "=r"((r)[26]), "=r"((r)[27]), \
          "=r"((r)[28]), "=r"((r)[29]), "=r"((r)[30]), "=r"((r)[31]) \
        : "r"(ta))

__device__ __forceinline__ uint64_t sdesc(uint32_t addr){
  const uint64_t base = (2ull << 61) | (1ull << 46) | (64ull << 32) | (1ull << 16);
  return base | ((uint64_t)(addr >> 4) & 0x3FFF);
}

__device__ __forceinline__ void mma_ss_f16(uint32_t d, uint64_t ad, uint64_t bd, uint32_t idesc, uint32_t en){
  asm volatile(
    "{\n\t.reg .pred p;\n\tsetp.ne.u32 p, %5, 0;\n\t"
    "tcgen05.mma.cta_group::1.kind::f16 [%0], %1, %2, %3, {%4, %4, %4, %4}, p;\n\t}"
    :: "r"(d), "l"(ad), "l"(bd), "r"(idesc), "r"(0u), "r"(en) : "memory");
}

// idesc: dtype F32, atype/btype BF16, N=64, M=128 (proven atom geometry)
#define IDESC_128x64 ((1u<<4) | (1u<<7) | (1u<<10) | ((64u/8u)<<17) | ((128u/16u)<<24))
#endif // HAS_TCGEN05

// ---------------- scratch (device globals; no allocations allowed) ----------------
#define SCRATCH_FLOATS (524288 + 2097152 + 262144 + 12*TC)
__device__ float g_scratch[SCRATCH_FLOATS];

// bf16 pool
#define WSZ (2048*2048)
#define BF_EXTRA (2*524288 + 4*262144 + 2*131072 + 2*262144)
__device__ __align__(16) __nv_bfloat16 g_bf16[4*TC + 8*WSZ + BF_EXTRA];

// chunked-scan scratch
#define SCAN_FLOATS (3*1024*4096 + 2*1024*2048 + 1024*64)
__device__ float g_scan[SCAN_FLOATS];

// ---------------- generalized tcgen05 split-bf16 GEMM (3 CTAs/SM) ------------------
#define GEMM_SMEM_ALLOC 66560   // 1024 + 65536

__global__ void __launch_bounds__(256, 3)
#if HAS_TCGEN05
__cluster_dims__(1, 1, 1)
#endif
gemm_tcg(
    const __nv_bfloat16* __restrict__ Ah, const __nv_bfloat16* __restrict__ Al, int lda,
    const __nv_bfloat16* __restrict__ Bh0, const __nv_bfloat16* __restrict__ Bl0,
    const __nv_bfloat16* __restrict__ Bh1, const __nv_bfloat16* __restrict__ Bl1,
    const __nv_bfloat16* __restrict__ Bh2, const __nv_bfloat16* __restrict__ Bl2, int ldb,
    float* C0, float* C1, float* C2, int ldc,
    int kchunks, int kslice, long long cslice, int acol0, int acolz)
{
  extern __shared__ __align__(1024) char smem[];
  int tid = threadIdx.x;
  int z = blockIdx.z;
  int m0 = blockIdx.y * 128, n0 = blockIdx.x * 128;

  const __nv_bfloat16 *Bh, *Bl;
  float* C;
  int akoff, bkoff;
  if (kslice > 0){
    Bh = Bh0; Bl = Bl0;
    C = C0 + (long long)z * cslice;
    akoff = acol0 + z * kslice;
    bkoff = z * kslice;
  } else {
    Bh = (z == 0) ? Bh0 : (z == 1) ? Bh1 : Bh2;
    Bl = (z == 0) ? Bl0 : (z == 1) ? Bl1 : Bl2;
    C  = (z == 0) ? C0  : (z == 1) ? C1  : C2;
    akoff = acol0 + z * acolz;
    bkoff = 0;
  }

#if HAS_TCGEN05
  uint32_t sb = smem_u32(smem);
  int wid = tid >> 5, lid = tid & 31;

  if (wid == 0) { T5_ALLOC(sb, 128); T5_RELINQ(); }
  if (tid == 0) { MBAR_INIT(sb + 8, 1); }
  __syncthreads();
  uint32_t tmem;
  asm volatile("ld.shared.b32 %0, [%1];" : "=r"(tmem) : "r"(sb));

  int smoff[4];
  int offA[4], offB[4];
  #pragma unroll
  for (int i = 0; i < 4; i++){
    int e = tid + (i << 8);
    int row = e >> 3, seg = e & 7;
    smoff[i] = SW128(row*128 + seg*16);
    offA[i] = (m0 + row)*lda + seg*8;
    offB[i] = (n0 + row)*ldb + seg*8;
  }

  uint4 pf[8];
  #pragma unroll
  for (int i = 0; i < 4; i++){
    pf[i]     = *(const uint4*)(Bh + offB[i] + bkoff);
    pf[4 + i] = *(const uint4*)(Bl + offB[i] + bkoff);
  }

  for (int c = 0; c < kchunks; c++){
    int k0 = c * 64;
    #pragma unroll
    for (int i = 0; i < 4; i++){
      *(uint4*)(smem + 1024 + 32768 + smoff[i]) = pf[i];
      *(uint4*)(smem + 1024 + 49152 + smoff[i]) = pf[4 + i];
    }
    #pragma unroll
    for (int i = 0; i < 4; i++){
      uint4 va = *(const uint4*)(Ah + offA[i] + akoff + k0);
      uint4 vb = *(const uint4*)(Al + offA[i] + akoff + k0);
      *(uint4*)(smem + 1024         + smoff[i]) = va;
      *(uint4*)(smem + 1024 + 16384 + smoff[i]) = vb;
    }
    FENCE_ASYNC();
    __syncthreads();

    if (c + 1 < kchunks){
      int k1 = (c + 1) * 64;
      #pragma unroll
      for (int i = 0; i < 4; i++){
        pf[i]     = *(const uint4*)(Bh + offB[i] + bkoff + k1);
        pf[4 + i] = *(const uint4*)(Bl + offB[i] + bkoff + k1);
      }
    }

    if (wid == 0 && elect1()){
      uint64_t dah  = sdesc(sb + 1024);
      uint64_t dal  = sdesc(sb + 1024 + 16384);
      uint64_t dbh0 = sdesc(sb + 1024 + 32768);
      uint64_t dbh1 = sdesc(sb + 1024 + 32768 + 8192);
      uint64_t dbl0 = sdesc(sb + 1024 + 49152);
      uint64_t dbl1 = sdesc(sb + 1024 + 49152 + 8192);
      #pragma unroll
      for (int ks = 0; ks < 4; ks++){
        uint64_t off = 2*ks;
        uint32_t en0 = (c | ks) ? 1u : 0u;
        mma_ss_f16(tmem,      dah + off, dbh0 + off, IDESC_128x64, en0);
        mma_ss_f16(tmem,      dal + off, dbh0 + off, IDESC_128x64, 1u);
        mma_ss_f16(tmem,      dah + off, dbl0 + off, IDESC_128x64, 1u);
        mma_ss_f16(tmem + 64, dah + off, dbh1 + off, IDESC_128x64, en0);
        mma_ss_f16(tmem + 64, dal + off, dbh1 + off, IDESC_128x64, 1u);
        mma_ss_f16(tmem + 64, dah + off, dbl1 + off, IDESC_128x64, 1u);
      }
      T5_COMMIT(sb + 8);
    }
    MBAR_WAIT(sb + 8, c & 1);
    __syncthreads();
  }

  T5_FENCE_AFTER();

  {
    int half = wid >> 2, wq = wid & 3;
    #pragma unroll
    for (int nb = 0; nb < 2; nb++){
      uint32_t rr[32];
      LDTM_X32(rr, tmem + half*64 + nb*32);
      T5_WAIT_LD();
      float4* cp = (float4*)(C + (size_t)(m0 + wq*32 + lid) * ldc + n0 + half*64 + nb*32);
      #pragma unroll
      for (int q = 0; q < 8; q++)
        cp[q] = make_float4(__uint_as_float(rr[4*q]),   __uint_as_float(rr[4*q+1]),
                            __uint_as_float(rr[4*q+2]), __uint_as_float(rr[4*q+3]));
    }
  }
  __syncthreads();
  if (tid == 0) { MBAR_INVAL(sb + 8); }
  __syncthreads();
  if (wid == 0) { T5_DEALLOC(tmem, 128); }

#else
  int K = kchunks * 64;
  for (int idx = tid; idx < 128*128; idx += 256){
    int mi = idx >> 7, ni = idx & 127;
    float s = 0.f;
    for (int k = 0; k < K; k++){
      float av = __bfloat162float(Ah[(size_t)(m0+mi)*lda + akoff + k]) +
                 __bfloat162float(Al[(size_t)(m0+mi)*lda + akoff + k]);
      float bv = __bfloat162float(Bh[(size_t)(n0+ni)*ldb + bkoff + k]) +
                 __bfloat162float(Bl[(size_t)(n0+ni)*ldb + bkoff + k]);
      s += av * bv;
    }
    C[(size_t)(m0+mi)*ldc + n0 + ni] = s;
  }
#endif
}

// ---------------- operand-prep kernels ----------------
__global__ void splitf(const float* __restrict__ s, __nv_bfloat16* __restrict__ hi,
                       __nv_bfloat16* __restrict__ lo, int n)
{
  int i = blockIdx.x*256 + threadIdx.x;
  if (i < n){
    float f = s[i];
    __nv_bfloat16 h = __float2bfloat16(f);
    hi[i] = h;
    lo[i] = __float2bfloat16(f - __bfloat162float(h));
  }
}

__global__ void __launch_bounds__(256) tsplit(
    const float* __restrict__ Wr, const float* __restrict__ Wk,
    const float* __restrict__ Wv, const float* __restrict__ Wo,
    __nv_bfloat16* __restrict__ out)
{
  const float* W = (blockIdx.z == 0) ? Wr : (blockIdx.z == 1) ? Wk : (blockIdx.z == 2) ? Wv : Wo;
  __nv_bfloat16* Th = out + (size_t)blockIdx.z * 2 * WSZ;
  __nv_bfloat16* Tl = Th + WSZ;
  __shared__ float s[32][33];
  int nb = blockIdx.x*32, kb = blockIdx.y*32;
  int tid = threadIdx.x;

  #pragma unroll
  for (int e = tid; e < 1024; e += 256){
    int rr = e >> 5, cc = e & 31;
    s[rr][cc] = W[(size_t)(kb+rr)*2048 + nb + cc];
  }
  __syncthreads();

  #pragma unroll
  for (int e = tid; e < 512; e += 256){
    int n = e >> 4, kp = (e & 15) << 1;
    float f0 = s[kp][n],   f1 = s[kp+1][n];
    __nv_bfloat16 h0 = __float2bfloat16(f0), h1 = __float2bfloat16(f1);
    __nv_bfloat162 hv; hv.x = h0; hv.y = h1;
    __nv_bfloat162 lv;
    lv.x = __float2bfloat16(f0 - __bfloat162float(h0));
    lv.y = __float2bfloat16(f1 - __bfloat162float(h1));
    size_t oi = ((size_t)(nb+n)*2048 + kb + kp) >> 1;
    ((__nv_bfloat162*)Th)[oi] = hv;
    ((__nv_bfloat162*)Tl)[oi] = lv;
  }
}

__global__ void build_bcatT(const float* __restrict__ w1, const float* __restrict__ a1,
                            const float* __restrict__ v1,
                            __nv_bfloat16* __restrict__ Th, __nv_bfloat16* __restrict__ Tl)
{
  int i = blockIdx.x*256 + threadIdx.x;
  if (i >= 256*2048) return;
  int n = i >> 11, k = i & 2047;
  float f;
  if      (n <  96) f = w1[k*96 + n];
  else if (n < 192) f = a1[k*96 + n - 96];
  else              f = v1[k*64 + n - 192];
  __nv_bfloat16 h = __float2bfloat16(f);
  Th[i] = h;
  Tl[i] = __float2bfloat16(f - __bfloat162float(h));
}

__global__ void build_m2T(const float* __restrict__ w2, const float* __restrict__ a2,
                          const float* __restrict__ v2,
                          __nv_bfloat16* __restrict__ w2Th, __nv_bfloat16* __restrict__ w2Tl,
                          __nv_bfloat16* __restrict__ a2Th, __nv_bfloat16* __restrict__ a2Tl,
                          __nv_bfloat16* __restrict__ v2Th, __nv_bfloat16* __restrict__ v2Tl)
{
  int z = blockIdx.z;
  int ldk = (z == 2) ? 64 : 128;
  int Kz  = (z == 2) ? 64 : 96;
  int nel = 2048 * ldk;
  int i = blockIdx.x*256 + threadIdx.x;
  if (i >= nel) return;
  int kp = i & (ldk - 1), n = i / ldk;
  const float* M = (z == 0) ? w2 : (z == 1) ? a2 : v2;
  float f = (kp < Kz) ? M[(size_t)kp*2048 + n] : 0.f;
  __nv_bfloat16 h = __float2bfloat16(f);
  __nv_bfloat16* Th = (z == 0) ? w2Th : (z == 1) ? a2Th : v2Th;
  __nv_bfloat16* Tl = (z == 0) ? w2Tl : (z == 1) ? a2Tl : v2Tl;
  Th[i] = h;
  Tl[i] = __float2bfloat16(f - __bfloat162float(h));
}

__global__ void reduce_hcat(const float* __restrict__ part,
                            __nv_bfloat16* __restrict__ hch, __nv_bfloat16* __restrict__ hcl)
{
  int i = blockIdx.x*256 + threadIdx.x;
  if (i >= 1024*256) return;
  float s = 0.f;
  #pragma unroll
  for (int z = 0; z < 8; z++) s += part[(size_t)z*1024*256 + i];
  int col = i & 255;
  if (col < 96) s = tanhf(s);
  __nv_bfloat16 h = __float2bfloat16(s);
  hch[i] = h;
  hcl[i] = __float2bfloat16(s - __bfloat162float(h));
}

// sum the four Wo split-K partials; also copy v_first into out[TC..2TC)
__global__ void reduce_out(const float* __restrict__ p0, const float* __restrict__ vf,
                           float* __restrict__ out, int copy_vf)
{
  int i = blockIdx.x*256 + threadIdx.x;
  if (i < TC){
    out[i] = (p0[i] + p0[TC + i]) + (p0[2*(size_t)TC + i] + p0[3*(size_t)TC + i]);
    if (copy_vf) out[TC + i] = vf[i];
  }
}

// ---------------- elementwise prep (256 threads = 4 heads, shfl reductions) --------
__device__ __forceinline__ float sigmoidf_(float x){ return 1.f/(1.f + expf(-x)); }

__global__ void __launch_bounds__(256) prep_kernel(
    float* __restrict__ k, float* __restrict__ v,
    const float* __restrict__ gw, const float* __restrict__ ga, const float* __restrict__ gv,
    const float* __restrict__ v_first, const float* __restrict__ mask,
    const float* __restrict__ w0, const float* __restrict__ a0, const float* __restrict__ v0,
    const float* __restrict__ k_k, const float* __restrict__ k_a,
    float* __restrict__ dec, float* __restrict__ asc, float* __restrict__ bsc,
    float* __restrict__ ksc, float* __restrict__ vsc)
{
  int t  = blockIdx.x >> 3;
  int hq = blockIdx.x & 7;
  int tid = threadIdx.x;
  int c  = (hq << 8) | tid;
  int idx = t*Cc + c;

  float kr  = k[idx];
  float kkv = kr * k_k[c];

  float sq = kkv*kkv;
  #pragma unroll
  for (int o = 16; o > 0; o >>= 1) sq += __shfl_xor_sync(0xffffffffu, sq, o);
  __shared__ float hs[8];
  if ((tid & 31) == 0) hs[tid >> 5] = sq;
  __syncthreads();
  int g = tid >> 6;
  float tot = hs[2*g] + hs[2*g + 1];
  float kkn = kkv / fmaxf(sqrtf(tot), 1e-12f);

  float av = sigmoidf_(a0[c] + ga[idx]);
  float m  = mask[t];

  float y  = w0[c] + gw[idx];
  float z  = -y;
  float sp = (z > 20.f) ? z : log1pf(expf(z));
  float w  = -sp - 0.6f;
  float d  = expf(-expf(w));
  d = d*m + (1.f - m);

  float vr = v[idx];
  float sv = sigmoidf_(v0[c] + gv[idx]);
  float vm = fmaf(v_first[idx] - vr, sv, vr);

  float ku = kr * fmaf(av - 1.f, k_a[c], 1.f);

  k[idx]   = ku;
  v[idx]   = vm;
  dec[idx] = d;
  ksc[idx] = ku * m;
  vsc[idx] = vm * m;
  asc[idx] = -kkn * m;
  bsc[idx] = kkn * av * m;
}

// ================= chunked RWKV-7 scan (WY/UT-transform) =================
#define OGAM 0
#define OAH  2145
#define OBB  4225
#define OKB  6305
#define ORH  8385
#define OVS  10465
#define OWS  12545
#define OZV  14625
#define OT1  16705
#define OT2  17729
#define OLB  18753
#define OLK  19777
#define S1_SMEM_FLOATS 20801   // 83204 bytes -> 2 blocks/SM

__global__ void __launch_bounds__(256) scan_stage1(
    const float* __restrict__ dec, const float* __restrict__ r,
    const float* __restrict__ kq, const float* __restrict__ vq,
    const float* __restrict__ aq, const float* __restrict__ bq,
    float* __restrict__ U, float* __restrict__ F,
    float* __restrict__ RP, float* __restrict__ OL, float* __restrict__ GL)
{
  extern __shared__ float sm[];
  float* GAM = sm + OGAM;
  float* AH  = sm + OAH;
  float* BB  = sm + OBB;
  float* KB  = sm + OKB;
  float* RH  = sm + ORH;
  float* VS  = sm + OVS;
  float* WS  = sm + OWS;
  float* ZV  = sm + OZV;
  float* T1  = sm + OT1;
  float* T2  = sm + OT2;
  float* LB  = sm + OLB;
  float* LK  = sm + OLK;

  int p = blockIdx.x;
  int h = p >> 5, c = p & 31;
  int t0 = c * SL, hb = h << 6;
  int tid = threadIdx.x;

  // stage dec tile into WS (coalesced, all 256 threads), then cumprod from smem
  for (int e = tid; e < SL*64; e += 256){
    int t = e >> 6, j = e & 63;
    WS[t*65+j] = dec[(size_t)(t0+t)*Cc + hb + j];
  }
  __syncthreads();
  if (tid < 64){
    float g = 1.f;
    GAM[0*65 + tid] = 1.f;
    #pragma unroll
    for (int t = 0; t < SL; t++){
      g *= WS[t*65 + tid];
      GAM[(t+1)*65 + tid] = g;
    }
  }
  __syncthreads();

  for (int e = tid; e < SL*64; e += 256){
    int t = e >> 6, j = e & 63;
    size_t gi = (size_t)(t0+t)*Cc + hb + j;
    float gp = GAM[t*65 + j];
    float gt = GAM[(t+1)*65 + j];
    AH[t*65+j] = aq[gi] * gp;
    BB[t*65+j] = bq[gi] / gt;
    KB[t*65+j] = kq[gi] / gt;
    RH[t*65+j] = r[gi] * gt;
    VS[t*65+j] = vq[gi];
  }
  __syncthreads();

  {
    int t0i = (tid >> 4) << 1;
    int s0i = (tid & 15) << 1;
    float d1[4]={0,0,0,0}, d2[4]={0,0,0,0}, d3[4]={0,0,0,0}, d4[4]={0,0,0,0};
    for (int j = 0; j < 64; j++){
      float a0 = AH[t0i*65+j],     a1 = AH[(t0i+1)*65+j];
      float r0 = RH[t0i*65+j],     r1 = RH[(t0i+1)*65+j];
      float b0 = BB[s0i*65+j],     b1 = BB[(s0i+1)*65+j];
      float k0 = KB[s0i*65+j],     k1 = KB[(s0i+1)*65+j];
      d1[0]=fmaf(b0,a0,d1[0]); d1[1]=fmaf(b1,a0,d1[1]); d1[2]=fmaf(b0,a1,d1[2]); d1[3]=fmaf(b1,a1,d1[3]);
      d2[0]=fmaf(k0,a0,d2[0]); d2[1]=fmaf(k1,a0,d2[1]); d2[2]=fmaf(k0,a1,d2[2]); d2[3]=fmaf(k1,a1,d2[3]);
      d3[0]=fmaf(b0,r0,d3[0]); d3[1]=fmaf(b1,r0,d3[1]); d3[2]=fmaf(b0,r1,d3[2]); d3[3]=fmaf(b1,r1,d3[3]);
      d4[0]=fmaf(k0,r0,d4[0]); d4[1]=fmaf(k1,r0,d4[1]); d4[2]=fmaf(k0,r1,d4[2]); d4[3]=fmaf(k1,r1,d4[3]);
    }
    #pragma unroll
    for (int q = 0; q < 4; q++){
      int t = t0i + (q >> 1), s = s0i + (q & 1);
      T1[t*SL+s] = (s <  t) ? d1[q] : 0.f;
      T2[t*SL+s] = (s <  t) ? d2[q] : 0.f;
      LB[t*SL+s] = (s <= t) ? d3[q] : 0.f;
      LK[t*SL+s] = (s <= t) ? d4[q] : 0.f;
    }
  }
  __syncthreads();

  {
    int t = tid >> 3, j0 = (tid & 7) << 3;
    float zz[8] = {0,0,0,0,0,0,0,0};
    for (int s = 0; s < SL; s++){
      float t2 = T2[t*SL+s];
      #pragma unroll
      for (int q = 0; q < 8; q++) zz[q] = fmaf(t2, VS[s*65+j0+q], zz[q]);
    }
    #pragma unroll
    for (int q = 0; q < 8; q++){
      ZV[t*65+j0+q] = zz[q];
      WS[t*65+j0+q] = AH[t*65+j0+q];
    }
  }
  __syncthreads();

  if (tid < 128){
    int j = tid & 63;
    float* M = (tid < 64) ? WS : ZV;
    for (int t = 1; t < SL; t++){
      float acc = M[t*65+j];
      for (int s = 0; s < t; s++) acc += T1[t*SL+s] * M[s*65+j];
      M[t*65+j] = acc;
    }
  }
  __syncthreads();

  {
    int t = tid >> 3, j0 = (tid & 7) << 3;
    float rp[8], ol[8];
    #pragma unroll
    for (int q = 0; q < 8; q++){ rp[q] = RH[t*65+j0+q]; ol[q] = 0.f; }
    for (int s = 0; s <= t; s++){
      float lb = LB[t*SL+s], lk = LK[t*SL+s];
      #pragma unroll
      for (int q = 0; q < 8; q++){
        rp[q] = fmaf(lb, WS[s*65+j0+q], rp[q]);
        ol[q] = fmaf(lb, ZV[s*65+j0+q], fmaf(lk, VS[s*65+j0+q], ol[q]));
      }
    }
    #pragma unroll
    for (int q = 0; q < 8; q++){
      RP[(size_t)p*2048 + t*64 + j0 + q] = rp[q];
      OL[(size_t)p*2048 + t*64 + j0 + q] = ol[q];
    }
  }

  {
    int i0 = (tid >> 4) << 2;
    int j0 = (tid & 15) << 2;
    float u[16], f[16];
    #pragma unroll
    for (int q = 0; q < 16; q++){ u[q] = 0.f; f[q] = 0.f; }
    for (int t = 0; t < SL; t++){
      float ws[4], zv[4], vs[4], bb[4], kb[4];
      #pragma unroll
      for (int ii = 0; ii < 4; ii++){
        ws[ii] = WS[t*65+i0+ii];
        zv[ii] = ZV[t*65+i0+ii];
        vs[ii] = VS[t*65+i0+ii];
      }
      #pragma unroll
      for (int jj = 0; jj < 4; jj++){
        bb[jj] = BB[t*65+j0+jj];
        kb[jj] = KB[t*65+j0+jj];
      }
      #pragma unroll
      for (int ii = 0; ii < 4; ii++)
        #pragma unroll
        for (int jj = 0; jj < 4; jj++){
          u[ii*4+jj] = fmaf(ws[ii], bb[jj], u[ii*4+jj]);
          f[ii*4+jj] = fmaf(zv[ii], bb[jj], fmaf(vs[ii], kb[jj], f[ii*4+jj]));
        }
    }
    #pragma unroll
    for (int ii = 0; ii < 4; ii++)
      #pragma unroll
      for (int jj = 0; jj < 4; jj++){
        float glj = GAM[SL*65 + j0 + jj];
        U[(size_t)p*4096 + (i0+ii)*64 + j0 + jj] = u[ii*4+jj] * glj;
        F[(size_t)p*4096 + (i0+ii)*64 + j0 + jj] = f[ii*4+jj] * glj;
      }
  }
  if (tid < 64) GL[(size_t)p*64 + tid] = GAM[SL*65 + tid];
}

// stage2 parallelized over (head, 8-row blocks)
__global__ void __launch_bounds__(128) scan_stage2(
    const float* __restrict__ U, const float* __restrict__ F,
    const float* __restrict__ GL, float* __restrict__ S0out)
{
  int h  = blockIdx.x >> 3;
  int rb = blockIdx.x & 7;
  int i0 = rb * 8;
  int tid = threadIdx.x;
  int il = tid >> 4;
  int j0 = (tid & 15) * 4;
  __shared__ float Ss[8][65];
  __shared__ float Us[64*64];
  for (int e = tid; e < 8*65; e += 128) (&Ss[0][0])[e] = 0.f;
  __syncthreads();

  for (int c = 0; c < NCH; c++){
    size_t p = (size_t)(h*NCH + c);
    const float* Up = U + p*4096;
    const float* Fp = F + p*4096;
    const float* Gp = GL + p*64;
    float* S0p = S0out + p*4096;
    #pragma unroll
    for (int q = 0; q < 4; q++)
      S0p[(i0+il)*64 + j0 + q] = Ss[il][j0+q];
    for (int e = tid; e < 4096; e += 128) Us[e] = Up[e];
    __syncthreads();
    float acc[4];
    #pragma unroll
    for (int q = 0; q < 4; q++)
      acc[q] = Ss[il][j0+q] * Gp[j0+q] + Fp[(i0+il)*64 + j0 + q];
    for (int k = 0; k < 64; k++){
      float sik = Ss[il][k];
      #pragma unroll
      for (int q = 0; q < 4; q++) acc[q] = fmaf(sik, Us[k*64+j0+q], acc[q]);
    }
    __syncthreads();
    #pragma unroll
    for (int q = 0; q < 4; q++) Ss[il][j0+q] = acc[q];
    __syncthreads();
  }
}

// stage3 fused with residual; register-blocked 4t x 2i matmul tiles
__global__ void __launch_bounds__(256) scan_stage3(
    const float* __restrict__ RP, const float* __restrict__ OL,
    const float* __restrict__ S0,
    const float* __restrict__ r, const float* __restrict__ k,
    const float* __restrict__ v, const float* __restrict__ r_k,
    __nv_bfloat16* __restrict__ oh, __nv_bfloat16* __restrict__ ol)
{
  int p = blockIdx.x;
  int h = p >> 5, c = p & 31;
  int t0 = c * SL, hb = h << 6;
  int tid = threadIdx.x;
  __shared__ float S0s[64*65];
  __shared__ float RPs[2048];
  __shared__ float rsum[SL][2];
  for (int e = tid; e < 4096; e += 256) S0s[(e>>6)*65 + (e&63)] = S0[(size_t)p*4096 + e];
  for (int e = tid; e < 2048; e += 256) RPs[e] = RP[(size_t)p*2048 + e];
  __syncthreads();

  for (int e = tid; e < 2048; e += 256){
    int t = e >> 6, i = e & 63;
    size_t gi = (size_t)(t0+t)*Cc + hb + i;
    float pr = r[gi]*k[gi]*r_k[hb + i];
    #pragma unroll
    for (int o = 16; o > 0; o >>= 1) pr += __shfl_xor_sync(0xffffffffu, pr, o);
    if ((e & 31) == 0) rsum[t][(i >> 5) & 1] = pr;
  }
  __syncthreads();

  {
    int tg = tid >> 5;
    int tb = tg * 4;
    int ii = tid & 31;
    int i0 = ii * 2;
    float acc[4][2];
    #pragma unroll
    for (int q = 0; q < 4; q++)
      #pragma unroll
      for (int pq = 0; pq < 2; pq++)
        acc[q][pq] = OL[(size_t)p*2048 + (tb+q)*64 + i0 + pq];
    for (int j = 0; j < 64; j++){
      float s0a = S0s[i0*65 + j];
      float s0b = S0s[(i0+1)*65 + j];
      #pragma unroll
      for (int q = 0; q < 4; q++){
        float rp = RPs[(tb+q)*64 + j];
        acc[q][0] = fmaf(rp, s0a, acc[q][0]);
        acc[q][1] = fmaf(rp, s0b, acc[q][1]);
      }
    }
    #pragma unroll
    for (int q = 0; q < 4; q++){
      int t = tb + q;
      float rs = rsum[t][0] + rsum[t][1];
      #pragma unroll
      for (int pq = 0; pq < 2; pq++){
        size_t gi = (size_t)(t0+t)*Cc + hb + i0 + pq;
        float val = fmaf(rs, v[gi], acc[q][pq]);
        __nv_bfloat16 hh = __float2bfloat16(val);
        oh[gi] = hh;
        ol[gi] = __float2bfloat16(val - __bfloat162float(hh));
      }
    }
  }
}

// ---------------- host launcher ----------------
extern "C" void kernel_launch(void* const* d_in, const int* in_sizes, int n_in,
                              void* d_out, int out_size)
{
  const float* x        = (const float*)d_in[0];
  const float* v_first  = (const float*)d_in[1];
  const float* mask     = (const float*)d_in[2];
  const float* w0       = (const float*)d_in[3];
  const float* w1       = (const float*)d_in[4];
  const float* w2       = (const float*)d_in[5];
  const float* a0       = (const float*)d_in[6];
  const float* a1       = (const float*)d_in[7];
  const float* a2       = (const float*)d_in[8];
  const float* v0       = (const float*)d_in[9];
  const float* v1       = (const float*)d_in[10];
  const float* v2       = (const float*)d_in[11];
  const float* k_k      = (const float*)d_in[12];
  const float* k_a      = (const float*)d_in[13];
  const float* r_k      = (const float*)d_in[14];
  const float* Wr       = (const float*)d_in[15];
  const float* Wk       = (const float*)d_in[16];
  const float* Wv       = (const float*)d_in[17];
  const float* Wo       = (const float*)d_in[18];
  float* outf = (float*)d_out;

  float* S = nullptr;
  cudaGetSymbolAddress((void**)&S, g_scratch);
  __nv_bfloat16* BF = nullptr;
  cudaGetSymbolAddress((void**)&BF, g_bf16);
  float* SC = nullptr;
  cudaGetSymbolAddress((void**)&SC, g_scan);

  float* bcat = S;
  float* part = bcat + 524288;
  float* hcat = part + 2097152;
  float* gw   = hcat + 262144;
  float* ga   = gw  + TC;
  float* gv   = ga  + TC;
  float* r    = gv  + TC;
  float* k    = r   + TC;
  float* v    = k   + TC;
  float* dec  = v   + TC;
  float* asc  = dec + TC;
  float* bsc  = asc + TC;
  float* ksc  = bsc + TC;
  float* vsc  = ksc + TC;
  float* wop  = gw;            // Wo split-K(4) partials (4*TC) reuse gw..r (dead by then)

  __nv_bfloat16* xh = BF;
  __nv_bfloat16* xl = xh + TC;
  __nv_bfloat16* oh = xl + TC;
  __nv_bfloat16* ol = oh + TC;
  __nv_bfloat16* Wt = ol + TC;
  __nv_bfloat16* Wrh = Wt + 0*WSZ, *Wrl = Wt + 1*WSZ;
  __nv_bfloat16* Wkh = Wt + 2*WSZ, *Wkl = Wt + 3*WSZ;
  __nv_bfloat16* Wvh = Wt + 4*WSZ, *Wvl = Wt + 5*WSZ;
  __nv_bfloat16* Woh = Wt + 6*WSZ, *Wol = Wt + 7*WSZ;
  __nv_bfloat16* ext  = Wt + 8*WSZ;
  __nv_bfloat16* bcTh = ext;
  __nv_bfloat16* bcTl = bcTh + 524288;
  __nv_bfloat16* w2Th = bcTl + 524288;
  __nv_bfloat16* w2Tl = w2Th + 262144;
  __nv_bfloat16* a2Th = w2Tl + 262144;
  __nv_bfloat16* a2Tl = a2Th + 262144;
  __nv_bfloat16* v2Th = a2Tl + 262144;
  __nv_bfloat16* v2Tl = v2Th + 131072;
  __nv_bfloat16* hch  = v2Tl + 131072;
  __nv_bfloat16* hcl  = hch + 262144;

  float* scS0 = SC;
  float* scU  = scS0 + 1024*4096;
  float* scF  = scU  + 1024*4096;
  float* scRP = scF  + 1024*4096;
  float* scOL = scRP + 1024*2048;
  float* scGL = scOL + 1024*2048;

  cudaFuncSetAttribute(gemm_tcg, cudaFuncAttributeMaxDynamicSharedMemorySize, GEMM_SMEM_ALLOC);
  cudaFuncSetAttribute(scan_stage1, cudaFuncAttributeMaxDynamicSharedMemorySize, S1_SMEM_FLOATS*4);

  // 0) operand prep
  splitf<<<TC/256, 256>>>(x, xh, xl, TC);                                     // 1
  build_bcatT<<<(256*2048)/256, 256>>>(w1, a1, v1, bcTh, bcTl);               // 2
  build_m2T<<<dim3(1024,1,3), 256>>>(w2, a2, v2, w2Th, w2Tl, a2Th, a2Tl, v2Th, v2Tl); // 3
  tsplit<<<dim3(64,64,4), 256>>>(Wr, Wk, Wv, Wo, Wt);                         // 4 (profiled)

  // 1) big GEMMs: r,k,v = x @ {Wr,Wk,Wv}
  {
    dim3 grid(16, 8, 3);
    gemm_tcg<<<grid, 256, GEMM_SMEM_ALLOC>>>(
        xh, xl, 2048,
        Wrh, Wrl, Wkh, Wkl, Wvh, Wvl, 2048,
        r, k, v, 2048,
        32, 0, 0LL, 0, 0);
  }

  // 2) thin GEMM (split-K 8)
  {
    dim3 grid(2, 8, 8);
    gemm_tcg<<<grid, 256, GEMM_SMEM_ALLOC>>>(
        xh, xl, 2048,
        bcTh, bcTl, bcTh, bcTl, bcTh, bcTl, 2048,
        part, part, part, 256,
        4, 256, 262144LL, 0, 0);
  }
  reduce_hcat<<<1024, 256>>>(part, hch, hcl);

  // 3) mid GEMMs
  {
    dim3 gwa(16, 8, 2);
    gemm_tcg<<<gwa, 256, GEMM_SMEM_ALLOC>>>(
        hch, hcl, 256,
        w2Th, w2Tl, a2Th, a2Tl, a2Th, a2Tl, 128,
        gw, ga, ga, 2048,
        2, 0, 0LL, 0, 96);
    dim3 gv_(16, 8, 1);
    gemm_tcg<<<gv_, 256, GEMM_SMEM_ALLOC>>>(
        hch, hcl, 256,
        v2Th, v2Tl, v2Th, v2Tl, v2Th, v2Tl, 64,
        gv, gv, gv, 2048,
        1, 0, 0LL, 192, 0);
  }

  // 4) elementwise prep
  prep_kernel<<<Tt*8, 256>>>(k, v, gw, ga, gv, v_first, mask,
                             w0, a0, v0, k_k, k_a,
                             dec, asc, bsc, ksc, vsc);

  // 5) chunked scan
  scan_stage1<<<Hh*NCH, 256, S1_SMEM_FLOATS*4>>>(dec, r, ksc, vsc, asc, bsc,
                                                 scU, scF, scRP, scOL, scGL);
  scan_stage2<<<Hh*8, 128>>>(scU, scF, scGL, scS0);
  scan_stage3<<<Hh*NCH, 256>>>(scRP, scOL, scS0, r, k, v, r_k, oh, ol);

  // 6) final GEMM: out = o @ Wo via split-K(4) + reduce (+ v_first copy fused)
  {
    dim3 grid(16, 8, 4);
    gemm_tcg<<<grid, 256, GEMM_SMEM_ALLOC>>>(
        oh, ol, 2048,
        Woh, Wol, Woh, Wol, Woh, Wol, 2048,
        wop, wop, wop, 2048,
        8, /*kslice=*/512, /*cslice=*/(long long)TC, 0, 0);
  }
  reduce_out<<<TC/256, 256>>>(wop, v_first, outf, (out_size >= 2*TC) ? 1 : 0);
}

// round 16
// speedup vs baseline: 1.1095x; 1.1095x over previous
#include <cuda_runtime.h>
#include <cuda_bf16.h>
#include <math.h>
#include <stdint.h>

// Problem constants
#define Tt 1024
#define Cc 2048
#define Hh 32
#define Nn 64
#define TC (Tt*Cc)          // 2097152
#define SL 32               // scan chunk length
#define NCH (Tt/SL)         // 32 chunks

// tcgen05 available only in architecture-specific compilation passes
#if defined(__CUDA_ARCH_FEAT_SM103_ALL) || defined(__CUDA_ARCH_FEAT_SM100_ALL) || defined(__CUDA_ARCH_SPECIFIC__)
#define HAS_TCGEN05 1
#else
#define HAS_TCGEN05 0
#endif

// ---------------- tcgen05 / mbarrier helpers (sm_103a) ----------------
__device__ __forceinline__ uint32_t smem_u32(const void* p){
  uint32_t a;
  asm("{ .reg .u64 t; cvta.to.shared.u64 t, %1; cvt.u32.u64 %0, t; }" : "=r"(a) : "l"(p));
  return a;
}

#define SW128(x) ((x) ^ (((x) >> 3) & 0x70))

#if HAS_TCGEN05
__device__ __forceinline__ uint32_t elect1(){
  uint32_t r;
  asm volatile("{\n\t.reg .pred p;\n\telect.sync _|p, 0xFFFFFFFF;\n\tselp.b32 %0, 1, 0, p;\n\t}" : "=r"(r));
  return r;
}

#define T5_ALLOC(sa, n)   asm volatile("tcgen05.alloc.cta_group::1.sync.aligned.shared::cta.b32 [%0], %1;" :: "r"(sa), "r"(n) : "memory")
#define T5_DEALLOC(t, n)  asm volatile("tcgen05.dealloc.cta_group::1.sync.aligned.b32 %0, %1;" :: "r"(t), "r"(n))
#define T5_RELINQ()       asm volatile("tcgen05.relinquish_alloc_permit.cta_group::1.sync.aligned;")
#define T5_COMMIT(mb)     asm volatile("tcgen05.commit.cta_group::1.mbarrier::arrive::one.shared::cluster.b64 [%0];" :: "r"(mb) : "memory")
#define T5_FENCE_AFTER()  asm volatile("tcgen05.fence::after_thread_sync;" ::: "memory")
#define T5_WAIT_LD()      asm volatile("tcgen05.wait::ld.sync.aligned;" ::: "memory")
#define FENCE_ASYNC()     asm volatile("fence.proxy.async.shared::cta;" ::: "memory")

#define MBAR_INIT(mb, cnt) asm volatile("mbarrier.init.shared.b64 [%0], %1;" :: "r"(mb), "r"(cnt) : "memory")
#define MBAR_INVAL(mb)     asm volatile("mbarrier.inval.shared.b64 [%0];" :: "r"(mb) : "memory")

#define MBAR_WAIT(mb, ph) do { \
  uint32_t _m = (mb), _p = (ph), _d; \
  asm volatile("{\n\t.reg .pred p;\n\tmbarrier.try_wait.parity.acquire.cta.shared::cta.b64 p, [%1], %2;\n\tselp.b32 %0, 1, 0, p;\n\t}" \
               : "=r"(_d) : "r"(_m), "r"(_p) : "memory"); \
  while (!_d) { \
    asm volatile("{\n\t.reg .pred p;\n\tmbarrier.try_wait.parity.acquire.cta.shared::cta.b64 p, [%1], %2, 0x989680;\n\tselp.b32 %0, 1, 0, p;\n\t}" \
                 : "=r"(_d) : "r"(_m), "r"(_p) : "memory"); \
  } } while(0)

#define LDTM_X32(r, ta) \
    asm volatile( \
        "tcgen05.ld.sync.aligned.32x32b.x32.b32 " \
        "{%0, %1, %2, %3, %4, %5, %6, %7, " \
        " %8, %9, %10, %11, %12, %13, %14, %15, " \
        " %16, %17, %18, %19, %20, %21, %22, %23, " \
        " %24, %25, %26, %27, %28, %29, %30, %31}, [%32];" \
        : "=r"((r)[0]),  "=r"((r)[1]),  "=r"((r)[2]),  "=r"((r)[3]), \
          "=r"((r)[4]),  "=r"((r)[5]),  "=r"((r)[6]),  "=r"((r)[7]), \
          "=r"((r)[8]),  "=r"((r)[9]),  "=r"((r)[10]), "=r"((r)[11]), \
          "=r"((r)[12]), "=r"((r)[13]), "=r"((r)[14]), "=r"((r)[15]), \
          "=r"((r)[16]), "=r"((r)[17]), "=r"((r)[18]), "=r"((r)[19]), \
          "=r"((r)[20]), "=r"((r)[21]), "=r"((r)[22]), "=r"((r)[23]), \
          "=r"((r)[24]), "=r"((r)[25]), "=r"((r)[26]), "=r"((r)[27]), \
          "=r"((r)[28]), "=r"((r)[29]), "=r"((r)[30]), "=r"((r)[31]) \
        : "r"(ta))

__device__ __forceinline__ uint64_t sdesc(uint32_t addr){
  const uint64_t base = (2ull << 61) | (1ull << 46) | (64ull << 32) | (1ull << 16);
  return base | ((uint64_t)(addr >> 4) & 0x3FFF);
}

__device__ __forceinline__ void mma_ss_f16(uint32_t d, uint64_t ad, uint64_t bd, uint32_t idesc, uint32_t en){
  asm volatile(
    "{\n\t.reg .pred p;\n\tsetp.ne.u32 p, %5, 0;\n\t"
    "tcgen05.mma.cta_group::1.kind::f16 [%0], %1, %2, %3, {%4, %4, %4, %4}, p;\n\t}"
    :: "r"(d), "l"(ad), "l"(bd), "r"(idesc), "r"(0u), "r"(en) : "memory");
}

// idesc: dtype F32, atype/btype BF16, N=64, M=128 (proven atom geometry)
#define IDESC_128x64 ((1u<<4) | (1u<<7) | (1u<<10) | ((64u/8u)<<17) | ((128u/16u)<<24))
#endif // HAS_TCGEN05

// ---------------- scratch (device globals; no allocations allowed) ----------------
#define SCRATCH_FLOATS (524288 + 2097152 + 262144 + 12*TC)
__device__ float g_scratch[SCRATCH_FLOATS];

// bf16 pool
#define WSZ (2048*2048)
#define BF_EXTRA (2*524288 + 4*262144 + 2*131072 + 2*262144)
__device__ __align__(16) __nv_bfloat16 g_bf16[4*TC + 8*WSZ + BF_EXTRA];

// chunked-scan scratch
#define SCAN_FLOATS (3*1024*4096 + 2*1024*2048 + 1024*64)
__device__ float g_scan[SCAN_FLOATS];

// ---------------- generalized tcgen05 split-bf16 GEMM (3 CTAs/SM) ------------------
#define GEMM_SMEM_ALLOC 66560   // 1024 + 65536

__global__ void __launch_bounds__(256, 3)
#if HAS_TCGEN05
__cluster_dims__(1, 1, 1)
#endif
gemm_tcg(
    const __nv_bfloat16* __restrict__ Ah, const __nv_bfloat16* __restrict__ Al, int lda,
    const __nv_bfloat16* __restrict__ Bh0, const __nv_bfloat16* __restrict__ Bl0,
    const __nv_bfloat16* __restrict__ Bh1, const __nv_bfloat16* __restrict__ Bl1,
    const __nv_bfloat16* __restrict__ Bh2, const __nv_bfloat16* __restrict__ Bl2, int ldb,
    float* C0, float* C1, float* C2, int ldc,
    int kchunks, int kslice, long long cslice, int acol0, int acolz)
{
  extern __shared__ __align__(1024) char smem[];
  int tid = threadIdx.x;
  int z = blockIdx.z;
  int m0 = blockIdx.y * 128, n0 = blockIdx.x * 128;

  const __nv_bfloat16 *Bh, *Bl;
  float* C;
  int akoff, bkoff;
  if (kslice > 0){
    Bh = Bh0; Bl = Bl0;
    C = C0 + (long long)z * cslice;
    akoff = acol0 + z * kslice;
    bkoff = z * kslice;
  } else {
    Bh = (z == 0) ? Bh0 : (z == 1) ? Bh1 : Bh2;
    Bl = (z == 0) ? Bl0 : (z == 1) ? Bl1 : Bl2;
    C  = (z == 0) ? C0  : (z == 1) ? C1  : C2;
    akoff = acol0 + z * acolz;
    bkoff = 0;
  }

#if HAS_TCGEN05
  uint32_t sb = smem_u32(smem);
  int wid = tid >> 5, lid = tid & 31;

  if (wid == 0) { T5_ALLOC(sb, 128); T5_RELINQ(); }
  if (tid == 0) { MBAR_INIT(sb + 8, 1); }
  __syncthreads();
  uint32_t tmem;
  asm volatile("ld.shared.b32 %0, [%1];" : "=r"(tmem) : "r"(sb));

  int smoff[4];
  int offA[4], offB[4];
  #pragma unroll
  for (int i = 0; i < 4; i++){
    int e = tid + (i << 8);
    int row = e >> 3, seg = e & 7;
    smoff[i] = SW128(row*128 + seg*16);
    offA[i] = (m0 + row)*lda + seg*8;
    offB[i] = (n0 + row)*ldb + seg*8;
  }

  uint4 pf[8];
  #pragma unroll
  for (int i = 0; i < 4; i++){
    pf[i]     = *(const uint4*)(Bh + offB[i] + bkoff);
    pf[4 + i] = *(const uint4*)(Bl + offB[i] + bkoff);
  }

  for (int c = 0; c < kchunks; c++){
    int k0 = c * 64;
    #pragma unroll
    for (int i = 0; i < 4; i++){
      *(uint4*)(smem + 1024 + 32768 + smoff[i]) = pf[i];
      *(uint4*)(smem + 1024 + 49152 + smoff[i]) = pf[4 + i];
    }
    #pragma unroll
    for (int i = 0; i < 4; i++){
      uint4 va = *(const uint4*)(Ah + offA[i] + akoff + k0);
      uint4 vb = *(const uint4*)(Al + offA[i] + akoff + k0);
      *(uint4*)(smem + 1024         + smoff[i]) = va;
      *(uint4*)(smem + 1024 + 16384 + smoff[i]) = vb;
    }
    FENCE_ASYNC();
    __syncthreads();

    if (c + 1 < kchunks){
      int k1 = (c + 1) * 64;
      #pragma unroll
      for (int i = 0; i < 4; i++){
        pf[i]     = *(const uint4*)(Bh + offB[i] + bkoff + k1);
        pf[4 + i] = *(const uint4*)(Bl + offB[i] + bkoff + k1);
      }
    }

    if (wid == 0 && elect1()){
      uint64_t dah  = sdesc(sb + 1024);
      uint64_t dal  = sdesc(sb + 1024 + 16384);
      uint64_t dbh0 = sdesc(sb + 1024 + 32768);
      uint64_t dbh1 = sdesc(sb + 1024 + 32768 + 8192);
      uint64_t dbl0 = sdesc(sb + 1024 + 49152);
      uint64_t dbl1 = sdesc(sb + 1024 + 49152 + 8192);
      #pragma unroll
      for (int ks = 0; ks < 4; ks++){
        uint64_t off = 2*ks;
        uint32_t en0 = (c | ks) ? 1u : 0u;
        mma_ss_f16(tmem,      dah + off, dbh0 + off, IDESC_128x64, en0);
        mma_ss_f16(tmem,      dal + off, dbh0 + off, IDESC_128x64, 1u);
        mma_ss_f16(tmem,      dah + off, dbl0 + off, IDESC_128x64, 1u);
        mma_ss_f16(tmem + 64, dah + off, dbh1 + off, IDESC_128x64, en0);
        mma_ss_f16(tmem + 64, dal + off, dbh1 + off, IDESC_128x64, 1u);
        mma_ss_f16(tmem + 64, dah + off, dbl1 + off, IDESC_128x64, 1u);
      }
      T5_COMMIT(sb + 8);
    }
    MBAR_WAIT(sb + 8, c & 1);
    __syncthreads();
  }

  T5_FENCE_AFTER();

  {
    int half = wid >> 2, wq = wid & 3;
    #pragma unroll
    for (int nb = 0; nb < 2; nb++){
      uint32_t rr[32];
      LDTM_X32(rr, tmem + half*64 + nb*32);
      T5_WAIT_LD();
      float4* cp = (float4*)(C + (size_t)(m0 + wq*32 + lid) * ldc + n0 + half*64 + nb*32);
      #pragma unroll
      for (int q = 0; q < 8; q++)
        cp[q] = make_float4(__uint_as_float(rr[4*q]),   __uint_as_float(rr[4*q+1]),
                            __uint_as_float(rr[4*q+2]), __uint_as_float(rr[4*q+3]));
    }
  }
  __syncthreads();
  if (tid == 0) { MBAR_INVAL(sb + 8); }
  __syncthreads();
  if (wid == 0) { T5_DEALLOC(tmem, 128); }

#else
  int K = kchunks * 64;
  for (int idx = tid; idx < 128*128; idx += 256){
    int mi = idx >> 7, ni = idx & 127;
    float s = 0.f;
    for (int k = 0; k < K; k++){
      float av = __bfloat162float(Ah[(size_t)(m0+mi)*lda + akoff + k]) +
                 __bfloat162float(Al[(size_t)(m0+mi)*lda + akoff + k]);
      float bv = __bfloat162float(Bh[(size_t)(n0+ni)*ldb + bkoff + k]) +
                 __bfloat162float(Bl[(size_t)(n0+ni)*ldb + bkoff + k]);
      s += av * bv;
    }
    C[(size_t)(m0+mi)*ldc + n0 + ni] = s;
  }
#endif
}

// ---------------- operand-prep kernels ----------------
__global__ void splitf(const float* __restrict__ s, __nv_bfloat16* __restrict__ hi,
                       __nv_bfloat16* __restrict__ lo, int n)
{
  int i = blockIdx.x*256 + threadIdx.x;
  if (i < n){
    float f = s[i];
    __nv_bfloat16 h = __float2bfloat16(f);
    hi[i] = h;
    lo[i] = __float2bfloat16(f - __bfloat162float(h));
  }
}

__global__ void __launch_bounds__(256) tsplit(
    const float* __restrict__ Wr, const float* __restrict__ Wk,
    const float* __restrict__ Wv, const float* __restrict__ Wo,
    __nv_bfloat16* __restrict__ out)
{
  const float* W = (blockIdx.z == 0) ? Wr : (blockIdx.z == 1) ? Wk : (blockIdx.z == 2) ? Wv : Wo;
  __nv_bfloat16* Th = out + (size_t)blockIdx.z * 2 * WSZ;
  __nv_bfloat16* Tl = Th + WSZ;
  __shared__ float s[32][33];
  int nb = blockIdx.x*32, kb = blockIdx.y*32;
  int tid = threadIdx.x;

  #pragma unroll
  for (int e = tid; e < 1024; e += 256){
    int rr = e >> 5, cc = e & 31;
    s[rr][cc] = W[(size_t)(kb+rr)*2048 + nb + cc];
  }
  __syncthreads();

  #pragma unroll
  for (int e = tid; e < 512; e += 256){
    int n = e >> 4, kp = (e & 15) << 1;
    float f0 = s[kp][n],   f1 = s[kp+1][n];
    __nv_bfloat16 h0 = __float2bfloat16(f0), h1 = __float2bfloat16(f1);
    __nv_bfloat162 hv; hv.x = h0; hv.y = h1;
    __nv_bfloat162 lv;
    lv.x = __float2bfloat16(f0 - __bfloat162float(h0));
    lv.y = __float2bfloat16(f1 - __bfloat162float(h1));
    size_t oi = ((size_t)(nb+n)*2048 + kb + kp) >> 1;
    ((__nv_bfloat162*)Th)[oi] = hv;
    ((__nv_bfloat162*)Tl)[oi] = lv;
  }
}

__global__ void build_bcatT(const float* __restrict__ w1, const float* __restrict__ a1,
                            const float* __restrict__ v1,
                            __nv_bfloat16* __restrict__ Th, __nv_bfloat16* __restrict__ Tl)
{
  int i = blockIdx.x*256 + threadIdx.x;
  if (i >= 256*2048) return;
  int n = i >> 11, k = i & 2047;
  float f;
  if      (n <  96) f = w1[k*96 + n];
  else if (n < 192) f = a1[k*96 + n - 96];
  else              f = v1[k*64 + n - 192];
  __nv_bfloat16 h = __float2bfloat16(f);
  Th[i] = h;
  Tl[i] = __float2bfloat16(f - __bfloat162float(h));
}

__global__ void build_m2T(const float* __restrict__ w2, const float* __restrict__ a2,
                          const float* __restrict__ v2,
                          __nv_bfloat16* __restrict__ w2Th, __nv_bfloat16* __restrict__ w2Tl,
                          __nv_bfloat16* __restrict__ a2Th, __nv_bfloat16* __restrict__ a2Tl,
                          __nv_bfloat16* __restrict__ v2Th, __nv_bfloat16* __restrict__ v2Tl)
{
  int z = blockIdx.z;
  int ldk = (z == 2) ? 64 : 128;
  int Kz  = (z == 2) ? 64 : 96;
  int nel = 2048 * ldk;
  int i = blockIdx.x*256 + threadIdx.x;
  if (i >= nel) return;
  int kp = i & (ldk - 1), n = i / ldk;
  const float* M = (z == 0) ? w2 : (z == 1) ? a2 : v2;
  float f = (kp < Kz) ? M[(size_t)kp*2048 + n] : 0.f;
  __nv_bfloat16 h = __float2bfloat16(f);
  __nv_bfloat16* Th = (z == 0) ? w2Th : (z == 1) ? a2Th : v2Th;
  __nv_bfloat16* Tl = (z == 0) ? w2Tl : (z == 1) ? a2Tl : v2Tl;
  Th[i] = h;
  Tl[i] = __float2bfloat16(f - __bfloat162float(h));
}

__global__ void reduce_hcat(const float* __restrict__ part,
                            __nv_bfloat16* __restrict__ hch, __nv_bfloat16* __restrict__ hcl)
{
  int i = blockIdx.x*256 + threadIdx.x;
  if (i >= 1024*256) return;
  float s = 0.f;
  #pragma unroll
  for (int z = 0; z < 8; z++) s += part[(size_t)z*1024*256 + i];
  int col = i & 255;
  if (col < 96) s = tanhf(s);
  __nv_bfloat16 h = __float2bfloat16(s);
  hch[i] = h;
  hcl[i] = __float2bfloat16(s - __bfloat162float(h));
}

// sum the two Wo split-K partials; also copy v_first into out[TC..2TC)
__global__ void reduce_out(const float* __restrict__ p0, const float* __restrict__ vf,
                           float* __restrict__ out, int copy_vf)
{
  int i = blockIdx.x*256 + threadIdx.x;
  if (i < TC){
    out[i] = p0[i] + p0[TC + i];
    if (copy_vf) out[TC + i] = vf[i];
  }
}

// ---------------- elementwise prep (256 threads = 4 heads, shfl reductions) --------
__device__ __forceinline__ float sigmoidf_(float x){ return 1.f/(1.f + expf(-x)); }

__global__ void __launch_bounds__(256) prep_kernel(
    float* __restrict__ k, float* __restrict__ v,
    const float* __restrict__ gw, const float* __restrict__ ga, const float* __restrict__ gv,
    const float* __restrict__ v_first, const float* __restrict__ mask,
    const float* __restrict__ w0, const float* __restrict__ a0, const float* __restrict__ v0,
    const float* __restrict__ k_k, const float* __restrict__ k_a,
    float* __restrict__ dec, float* __restrict__ asc, float* __restrict__ bsc,
    float* __restrict__ ksc, float* __restrict__ vsc)
{
  int t  = blockIdx.x >> 3;
  int hq = blockIdx.x & 7;
  int tid = threadIdx.x;
  int c  = (hq << 8) | tid;
  int idx = t*Cc + c;

  float kr  = k[idx];
  float kkv = kr * k_k[c];

  float sq = kkv*kkv;
  #pragma unroll
  for (int o = 16; o > 0; o >>= 1) sq += __shfl_xor_sync(0xffffffffu, sq, o);
  __shared__ float hs[8];
  if ((tid & 31) == 0) hs[tid >> 5] = sq;
  __syncthreads();
  int g = tid >> 6;
  float tot = hs[2*g] + hs[2*g + 1];
  float kkn = kkv / fmaxf(sqrtf(tot), 1e-12f);

  float av = sigmoidf_(a0[c] + ga[idx]);
  float m  = mask[t];

  float y  = w0[c] + gw[idx];
  float z  = -y;
  float sp = (z > 20.f) ? z : log1pf(expf(z));
  float w  = -sp - 0.6f;
  float d  = expf(-expf(w));
  d = d*m + (1.f - m);

  float vr = v[idx];
  float sv = sigmoidf_(v0[c] + gv[idx]);
  float vm = fmaf(v_first[idx] - vr, sv, vr);

  float ku = kr * fmaf(av - 1.f, k_a[c], 1.f);

  k[idx]   = ku;
  v[idx]   = vm;
  dec[idx] = d;
  ksc[idx] = ku * m;
  vsc[idx] = vm * m;
  asc[idx] = -kkn * m;
  bsc[idx] = kkn * av * m;
}

// ================= chunked RWKV-7 scan (WY/UT-transform) =================
// WS eliminated: forward substitution runs in place on AH (W overwrites AH).
#define OGAM 0
#define OAH  2145
#define OBB  4225
#define OKB  6305
#define ORH  8385
#define OVS  10465
#define OZV  12545
#define OT1  14625
#define OT2  15649
#define OLB  16673
#define OLK  17697
#define S1_SMEM_FLOATS 18721   // 74884 bytes -> 3 blocks/SM

__global__ void __launch_bounds__(256, 3) scan_stage1(
    const float* __restrict__ dec, const float* __restrict__ r,
    const float* __restrict__ kq, const float* __restrict__ vq,
    const float* __restrict__ aq, const float* __restrict__ bq,
    float* __restrict__ U, float* __restrict__ F,
    float* __restrict__ RP, float* __restrict__ OL, float* __restrict__ GL)
{
  extern __shared__ float sm[];
  float* GAM = sm + OGAM;
  float* AH  = sm + OAH;    // staging for dec, then a-hat, then W (in-place subst)
  float* BB  = sm + OBB;
  float* KB  = sm + OKB;
  float* RH  = sm + ORH;
  float* VS  = sm + OVS;
  float* ZV  = sm + OZV;
  float* T1  = sm + OT1;
  float* T2  = sm + OT2;
  float* LB  = sm + OLB;
  float* LK  = sm + OLK;

  int p = blockIdx.x;
  int h = p >> 5, c = p & 31;
  int t0 = c * SL, hb = h << 6;
  int tid = threadIdx.x;

  // stage dec tile into AH (coalesced), cumprod from smem
  for (int e = tid; e < SL*64; e += 256){
    int t = e >> 6, j = e & 63;
    AH[t*65+j] = dec[(size_t)(t0+t)*Cc + hb + j];
  }
  __syncthreads();
  if (tid < 64){
    float g = 1.f;
    GAM[0*65 + tid] = 1.f;
    #pragma unroll
    for (int t = 0; t < SL; t++){
      g *= AH[t*65 + tid];
      GAM[(t+1)*65 + tid] = g;
    }
  }
  __syncthreads();

  for (int e = tid; e < SL*64; e += 256){
    int t = e >> 6, j = e & 63;
    size_t gi = (size_t)(t0+t)*Cc + hb + j;
    float gp = GAM[t*65 + j];
    float gt = GAM[(t+1)*65 + j];
    AH[t*65+j] = aq[gi] * gp;
    BB[t*65+j] = bq[gi] / gt;
    KB[t*65+j] = kq[gi] / gt;
    RH[t*65+j] = r[gi] * gt;
    VS[t*65+j] = vq[gi];
  }
  __syncthreads();

  {
    int t0i = (tid >> 4) << 1;
    int s0i = (tid & 15) << 1;
    float d1[4]={0,0,0,0}, d2[4]={0,0,0,0}, d3[4]={0,0,0,0}, d4[4]={0,0,0,0};
    for (int j = 0; j < 64; j++){
      float a0 = AH[t0i*65+j],     a1 = AH[(t0i+1)*65+j];
      float r0 = RH[t0i*65+j],     r1 = RH[(t0i+1)*65+j];
      float b0 = BB[s0i*65+j],     b1 = BB[(s0i+1)*65+j];
      float k0 = KB[s0i*65+j],     k1 = KB[(s0i+1)*65+j];
      d1[0]=fmaf(b0,a0,d1[0]); d1[1]=fmaf(b1,a0,d1[1]); d1[2]=fmaf(b0,a1,d1[2]); d1[3]=fmaf(b1,a1,d1[3]);
      d2[0]=fmaf(k0,a0,d2[0]); d2[1]=fmaf(k1,a0,d2[1]); d2[2]=fmaf(k0,a1,d2[2]); d2[3]=fmaf(k1,a1,d2[3]);
      d3[0]=fmaf(b0,r0,d3[0]); d3[1]=fmaf(b1,r0,d3[1]); d3[2]=fmaf(b0,r1,d3[2]); d3[3]=fmaf(b1,r1,d3[3]);
      d4[0]=fmaf(k0,r0,d4[0]); d4[1]=fmaf(k1,r0,d4[1]); d4[2]=fmaf(k0,r1,d4[2]); d4[3]=fmaf(k1,r1,d4[3]);
    }
    #pragma unroll
    for (int q = 0; q < 4; q++){
      int t = t0i + (q >> 1), s = s0i + (q & 1);
      T1[t*SL+s] = (s <  t) ? d1[q] : 0.f;
      T2[t*SL+s] = (s <  t) ? d2[q] : 0.f;
      LB[t*SL+s] = (s <= t) ? d3[q] : 0.f;
      LK[t*SL+s] = (s <= t) ? d4[q] : 0.f;
    }
  }
  __syncthreads();

  {
    int t = tid >> 3, j0 = (tid & 7) << 3;
    float zz[8] = {0,0,0,0,0,0,0,0};
    for (int s = 0; s < SL; s++){
      float t2 = T2[t*SL+s];
      #pragma unroll
      for (int q = 0; q < 8; q++) zz[q] = fmaf(t2, VS[s*65+j0+q], zz[q]);
    }
    #pragma unroll
    for (int q = 0; q < 8; q++) ZV[t*65+j0+q] = zz[q];
  }
  __syncthreads();

  // forward substitution in place: AH becomes W, ZV becomes Zv
  if (tid < 128){
    int j = tid & 63;
    float* M = (tid < 64) ? AH : ZV;
    for (int t = 1; t < SL; t++){
      float acc = M[t*65+j];
      for (int s = 0; s < t; s++) acc += T1[t*SL+s] * M[s*65+j];
      M[t*65+j] = acc;
    }
  }
  __syncthreads();

  {
    int t = tid >> 3, j0 = (tid & 7) << 3;
    float rp[8], ol[8];
    #pragma unroll
    for (int q = 0; q < 8; q++){ rp[q] = RH[t*65+j0+q]; ol[q] = 0.f; }
    for (int s = 0; s <= t; s++){
      float lb = LB[t*SL+s], lk = LK[t*SL+s];
      #pragma unroll
      for (int q = 0; q < 8; q++){
        rp[q] = fmaf(lb, AH[s*65+j0+q], rp[q]);
        ol[q] = fmaf(lb, ZV[s*65+j0+q], fmaf(lk, VS[s*65+j0+q], ol[q]));
      }
    }
    #pragma unroll
    for (int q = 0; q < 8; q++){
      RP[(size_t)p*2048 + t*64 + j0 + q] = rp[q];
      OL[(size_t)p*2048 + t*64 + j0 + q] = ol[q];
    }
  }

  {
    int i0 = (tid >> 4) << 2;
    int j0 = (tid & 15) << 2;
    float u[16], f[16];
    #pragma unroll
    for (int q = 0; q < 16; q++){ u[q] = 0.f; f[q] = 0.f; }
    for (int t = 0; t < SL; t++){
      float ws[4], zv[4], vs[4], bb[4], kb[4];
      #pragma unroll
      for (int ii = 0; ii < 4; ii++){
        ws[ii] = AH[t*65+i0+ii];
        zv[ii] = ZV[t*65+i0+ii];
        vs[ii] = VS[t*65+i0+ii];
      }
      #pragma unroll
      for (int jj = 0; jj < 4; jj++){
        bb[jj] = BB[t*65+j0+jj];
        kb[jj] = KB[t*65+j0+jj];
      }
      #pragma unroll
      for (int ii = 0; ii < 4; ii++)
        #pragma unroll
        for (int jj = 0; jj < 4; jj++){
          u[ii*4+jj] = fmaf(ws[ii], bb[jj], u[ii*4+jj]);
          f[ii*4+jj] = fmaf(zv[ii], bb[jj], fmaf(vs[ii], kb[jj], f[ii*4+jj]));
        }
    }
    #pragma unroll
    for (int ii = 0; ii < 4; ii++)
      #pragma unroll
      for (int jj = 0; jj < 4; jj++){
        float glj = GAM[SL*65 + j0 + jj];
        U[(size_t)p*4096 + (i0+ii)*64 + j0 + jj] = u[ii*4+jj] * glj;
        F[(size_t)p*4096 + (i0+ii)*64 + j0 + jj] = f[ii*4+jj] * glj;
      }
  }
  if (tid < 64) GL[(size_t)p*64 + tid] = GAM[SL*65 + tid];
}

// stage2 parallelized over (head, 8-row blocks)
__global__ void __launch_bounds__(128) scan_stage2(
    const float* __restrict__ U, const float* __restrict__ F,
    const float* __restrict__ GL, float* __restrict__ S0out)
{
  int h  = blockIdx.x >> 3;
  int rb = blockIdx.x & 7;
  int i0 = rb * 8;
  int tid = threadIdx.x;
  int il = tid >> 4;
  int j0 = (tid & 15) * 4;
  __shared__ float Ss[8][65];
  __shared__ float Us[64*64];
  for (int e = tid; e < 8*65; e += 128) (&Ss[0][0])[e] = 0.f;
  __syncthreads();

  for (int c = 0; c < NCH; c++){
    size_t p = (size_t)(h*NCH + c);
    const float* Up = U + p*4096;
    const float* Fp = F + p*4096;
    const float* Gp = GL + p*64;
    float* S0p = S0out + p*4096;
    #pragma unroll
    for (int q = 0; q < 4; q++)
      S0p[(i0+il)*64 + j0 + q] = Ss[il][j0+q];
    for (int e = tid; e < 4096; e += 128) Us[e] = Up[e];
    __syncthreads();
    float acc[4];
    #pragma unroll
    for (int q = 0; q < 4; q++)
      acc[q] = Ss[il][j0+q] * Gp[j0+q] + Fp[(i0+il)*64 + j0 + q];
    for (int k = 0; k < 64; k++){
      float sik = Ss[il][k];
      #pragma unroll
      for (int q = 0; q < 4; q++) acc[q] = fmaf(sik, Us[k*64+j0+q], acc[q]);
    }
    __syncthreads();
    #pragma unroll
    for (int q = 0; q < 4; q++) Ss[il][j0+q] = acc[q];
    __syncthreads();
  }
}

// stage3 fused with residual; register-blocked 4t x 2i matmul tiles
__global__ void __launch_bounds__(256) scan_stage3(
    const float* __restrict__ RP, const float* __restrict__ OL,
    const float* __restrict__ S0,
    const float* __restrict__ r, const float* __restrict__ k,
    const float* __restrict__ v, const float* __restrict__ r_k,
    __nv_bfloat16* __restrict__ oh, __nv_bfloat16* __restrict__ ol)
{
  int p = blockIdx.x;
  int h = p >> 5, c = p & 31;
  int t0 = c * SL, hb = h << 6;
  int tid = threadIdx.x;
  __shared__ float S0s[64*65];
  __shared__ float RPs[2048];
  __shared__ float rsum[SL][2];
  for (int e = tid; e < 4096; e += 256) S0s[(e>>6)*65 + (e&63)] = S0[(size_t)p*4096 + e];
  for (int e = tid; e < 2048; e += 256) RPs[e] = RP[(size_t)p*2048 + e];
  __syncthreads();

  for (int e = tid; e < 2048; e += 256){
    int t = e >> 6, i = e & 63;
    size_t gi = (size_t)(t0+t)*Cc + hb + i;
    float pr = r[gi]*k[gi]*r_k[hb + i];
    #pragma unroll
    for (int o = 16; o > 0; o >>= 1) pr += __shfl_xor_sync(0xffffffffu, pr, o);
    if ((e & 31) == 0) rsum[t][(i >> 5) & 1] = pr;
  }
  __syncthreads();

  {
    int tg = tid >> 5;
    int tb = tg * 4;
    int ii = tid & 31;
    int i0 = ii * 2;
    float acc[4][2];
    #pragma unroll
    for (int q = 0; q < 4; q++)
      #pragma unroll
      for (int pq = 0; pq < 2; pq++)
        acc[q][pq] = OL[(size_t)p*2048 + (tb+q)*64 + i0 + pq];
    for (int j = 0; j < 64; j++){
      float s0a = S0s[i0*65 + j];
      float s0b = S0s[(i0+1)*65 + j];
      #pragma unroll
      for (int q = 0; q < 4; q++){
        float rp = RPs[(tb+q)*64 + j];
        acc[q][0] = fmaf(rp, s0a, acc[q][0]);
        acc[q][1] = fmaf(rp, s0b, acc[q][1]);
      }
    }
    #pragma unroll
    for (int q = 0; q < 4; q++){
      int t = tb + q;
      float rs = rsum[t][0] + rsum[t][1];
      #pragma unroll
      for (int pq = 0; pq < 2; pq++){
        size_t gi = (size_t)(t0+t)*Cc + hb + i0 + pq;
        float val = fmaf(rs, v[gi], acc[q][pq]);
        __nv_bfloat16 hh = __float2bfloat16(val);
        oh[gi] = hh;
        ol[gi] = __float2bfloat16(val - __bfloat162float(hh));
      }
    }
  }
}

// ---------------- host launcher ----------------
extern "C" void kernel_launch(void* const* d_in, const int* in_sizes, int n_in,
                              void* d_out, int out_size)
{
  const float* x        = (const float*)d_in[0];
  const float* v_first  = (const float*)d_in[1];
  const float* mask     = (const float*)d_in[2];
  const float* w0       = (const float*)d_in[3];
  const float* w1       = (const float*)d_in[4];
  const float* w2       = (const float*)d_in[5];
  const float* a0       = (const float*)d_in[6];
  const float* a1       = (const float*)d_in[7];
  const float* a2       = (const float*)d_in[8];
  const float* v0       = (const float*)d_in[9];
  const float* v1       = (const float*)d_in[10];
  const float* v2       = (const float*)d_in[11];
  const float* k_k      = (const float*)d_in[12];
  const float* k_a      = (const float*)d_in[13];
  const float* r_k      = (const float*)d_in[14];
  const float* Wr       = (const float*)d_in[15];
  const float* Wk       = (const float*)d_in[16];
  const float* Wv       = (const float*)d_in[17];
  const float* Wo       = (const float*)d_in[18];
  float* outf = (float*)d_out;

  float* S = nullptr;
  cudaGetSymbolAddress((void**)&S, g_scratch);
  __nv_bfloat16* BF = nullptr;
  cudaGetSymbolAddress((void**)&BF, g_bf16);
  float* SC = nullptr;
  cudaGetSymbolAddress((void**)&SC, g_scan);

  float* bcat = S;
  float* part = bcat + 524288;
  float* hcat = part + 2097152;
  float* gw   = hcat + 262144;
  float* ga   = gw  + TC;
  float* gv   = ga  + TC;
  float* r    = gv  + TC;
  float* k    = r   + TC;
  float* v    = k   + TC;
  float* dec  = v   + TC;
  float* asc  = dec + TC;
  float* bsc  = asc + TC;
  float* ksc  = bsc + TC;
  float* vsc  = ksc + TC;
  float* wop  = gw;            // Wo split-K(2) partials (2*TC) reuse gw/ga (dead after prep)

  __nv_bfloat16* xh = BF;
  __nv_bfloat16* xl = xh + TC;
  __nv_bfloat16* oh = xl + TC;
  __nv_bfloat16* ol = oh + TC;
  __nv_bfloat16* Wt = ol + TC;
  __nv_bfloat16* Wrh = Wt + 0*WSZ, *Wrl = Wt + 1*WSZ;
  __nv_bfloat16* Wkh = Wt + 2*WSZ, *Wkl = Wt + 3*WSZ;
  __nv_bfloat16* Wvh = Wt + 4*WSZ, *Wvl = Wt + 5*WSZ;
  __nv_bfloat16* Woh = Wt + 6*WSZ, *Wol = Wt + 7*WSZ;
  __nv_bfloat16* ext  = Wt + 8*WSZ;
  __nv_bfloat16* bcTh = ext;
  __nv_bfloat16* bcTl = bcTh + 524288;
  __nv_bfloat16* w2Th = bcTl + 524288;
  __nv_bfloat16* w2Tl = w2Th + 262144;
  __nv_bfloat16* a2Th = w2Tl + 262144;
  __nv_bfloat16* a2Tl = a2Th + 262144;
  __nv_bfloat16* v2Th = a2Tl + 262144;
  __nv_bfloat16* v2Tl = v2Th + 131072;
  __nv_bfloat16* hch  = v2Tl + 131072;
  __nv_bfloat16* hcl  = hch + 262144;

  float* scS0 = SC;
  float* scU  = scS0 + 1024*4096;
  float* scF  = scU  + 1024*4096;
  float* scRP = scF  + 1024*4096;
  float* scOL = scRP + 1024*2048;
  float* scGL = scOL + 1024*2048;

  cudaFuncSetAttribute(gemm_tcg, cudaFuncAttributeMaxDynamicSharedMemorySize, GEMM_SMEM_ALLOC);
  cudaFuncSetAttribute(scan_stage1, cudaFuncAttributeMaxDynamicSharedMemorySize, S1_SMEM_FLOATS*4);

  // 0) operand prep
  splitf<<<TC/256, 256>>>(x, xh, xl, TC);                                     // 1
  build_bcatT<<<(256*2048)/256, 256>>>(w1, a1, v1, bcTh, bcTl);               // 2
  build_m2T<<<dim3(1024,1,3), 256>>>(w2, a2, v2, w2Th, w2Tl, a2Th, a2Tl, v2Th, v2Tl); // 3
  tsplit<<<dim3(64,64,4), 256>>>(Wr, Wk, Wv, Wo, Wt);                         // 4 (profiled)

  // 1) big GEMMs: r,k,v = x @ {Wr,Wk,Wv}
  {
    dim3 grid(16, 8, 3);
    gemm_tcg<<<grid, 256, GEMM_SMEM_ALLOC>>>(
        xh, xl, 2048,
        Wrh, Wrl, Wkh, Wkl, Wvh, Wvl, 2048,
        r, k, v, 2048,
        32, 0, 0LL, 0, 0);
  }

  // 2) thin GEMM (split-K 8)
  {
    dim3 grid(2, 8, 8);
    gemm_tcg<<<grid, 256, GEMM_SMEM_ALLOC>>>(
        xh, xl, 2048,
        bcTh, bcTl, bcTh, bcTl, bcTh, bcTl, 2048,
        part, part, part, 256,
        4, 256, 262144LL, 0, 0);
  }
  reduce_hcat<<<1024, 256>>>(part, hch, hcl);

  // 3) mid GEMMs
  {
    dim3 gwa(16, 8, 2);
    gemm_tcg<<<gwa, 256, GEMM_SMEM_ALLOC>>>(
        hch, hcl, 256,
        w2Th, w2Tl, a2Th, a2Tl, a2Th, a2Tl, 128,
        gw, ga, ga, 2048,
        2, 0, 0LL, 0, 96);
    dim3 gv_(16, 8, 1);
    gemm_tcg<<<gv_, 256, GEMM_SMEM_ALLOC>>>(
        hch, hcl, 256,
        v2Th, v2Tl, v2Th, v2Tl, v2Th, v2Tl, 64,
        gv, gv, gv, 2048,
        1, 0, 0LL, 192, 0);
  }

  // 4) elementwise prep
  prep_kernel<<<Tt*8, 256>>>(k, v, gw, ga, gv, v_first, mask,
                             w0, a0, v0, k_k, k_a,
                             dec, asc, bsc, ksc, vsc);

  // 5) chunked scan
  scan_stage1<<<Hh*NCH, 256, S1_SMEM_FLOATS*4>>>(dec, r, ksc, vsc, asc, bsc,
                                                 scU, scF, scRP, scOL, scGL);
  scan_stage2<<<Hh*8, 128>>>(scU, scF, scGL, scS0);
  scan_stage3<<<Hh*NCH, 256>>>(scRP, scOL, scS0, r, k, v, r_k, oh, ol);

  // 6) final GEMM: out = o @ Wo via split-K(2) + reduce (+ v_first copy fused)
  {
    dim3 grid(16, 8, 2);
    gemm_tcg<<<grid, 256, GEMM_SMEM_ALLOC>>>(
        oh, ol, 2048,
        Woh, Wol, Woh, Wol, Woh, Wol, 2048,
        wop, wop, wop, 2048,
        16, /*kslice=*/1024, /*cslice=*/(long long)TC, 0, 0);
  }
  reduce_out<<<TC/256, 256>>>(wop, v_first, outf, (out_size >= 2*TC) ? 1 : 0);
}

// round 17
// speedup vs baseline: 1.1511x; 1.0375x over previous
#include <cuda_runtime.h>
#include <cuda_bf16.h>
#include <math.h>
#include <stdint.h>

// Problem constants
#define Tt 1024
#define Cc 2048
#define Hh 32
#define Nn 64
#define TC (Tt*Cc)          // 2097152
#define SL 32               // scan chunk length
#define NCH (Tt/SL)         // 32 chunks

// tcgen05 available only in architecture-specific compilation passes
#if defined(__CUDA_ARCH_FEAT_SM103_ALL) || defined(__CUDA_ARCH_FEAT_SM100_ALL) || defined(__CUDA_ARCH_SPECIFIC__)
#define HAS_TCGEN05 1
#else
#define HAS_TCGEN05 0
#endif

// ---------------- tcgen05 / mbarrier helpers (sm_103a) ----------------
__device__ __forceinline__ uint32_t smem_u32(const void* p){
  uint32_t a;
  asm("{ .reg .u64 t; cvta.to.shared.u64 t, %1; cvt.u32.u64 %0, t; }" : "=r"(a) : "l"(p));
  return a;
}

#define SW128(x) ((x) ^ (((x) >> 3) & 0x70))

#if HAS_TCGEN05
__device__ __forceinline__ uint32_t elect1(){
  uint32_t r;
  asm volatile("{\n\t.reg .pred p;\n\telect.sync _|p, 0xFFFFFFFF;\n\tselp.b32 %0, 1, 0, p;\n\t}" : "=r"(r));
  return r;
}

#define T5_ALLOC(sa, n)   asm volatile("tcgen05.alloc.cta_group::1.sync.aligned.shared::cta.b32 [%0], %1;" :: "r"(sa), "r"(n) : "memory")
#define T5_DEALLOC(t, n)  asm volatile("tcgen05.dealloc.cta_group::1.sync.aligned.b32 %0, %1;" :: "r"(t), "r"(n))
#define T5_RELINQ()       asm volatile("tcgen05.relinquish_alloc_permit.cta_group::1.sync.aligned;")
#define T5_COMMIT(mb)     asm volatile("tcgen05.commit.cta_group::1.mbarrier::arrive::one.shared::cluster.b64 [%0];" :: "r"(mb) : "memory")
#define T5_FENCE_AFTER()  asm volatile("tcgen05.fence::after_thread_sync;" ::: "memory")
#define T5_WAIT_LD()      asm volatile("tcgen05.wait::ld.sync.aligned;" ::: "memory")
#define FENCE_ASYNC()     asm volatile("fence.proxy.async.shared::cta;" ::: "memory")

#define MBAR_INIT(mb, cnt) asm volatile("mbarrier.init.shared.b64 [%0], %1;" :: "r"(mb), "r"(cnt) : "memory")
#define MBAR_INVAL(mb)     asm volatile("mbarrier.inval.shared.b64 [%0];" :: "r"(mb) : "memory")

#define MBAR_WAIT(mb, ph) do { \
  uint32_t _m = (mb), _p = (ph), _d; \
  asm volatile("{\n\t.reg .pred p;\n\tmbarrier.try_wait.parity.acquire.cta.shared::cta.b64 p, [%1], %2;\n\tselp.b32 %0, 1, 0, p;\n\t}" \
               : "=r"(_d) : "r"(_m), "r"(_p) : "memory"); \
  while (!_d) { \
    asm volatile("{\n\t.reg .pred p;\n\tmbarrier.try_wait.parity.acquire.cta.shared::cta.b64 p, [%1], %2, 0x989680;\n\tselp.b32 %0, 1, 0, p;\n\t}" \
                 : "=r"(_d) : "r"(_m), "r"(_p) : "memory"); \
  } } while(0)

#define LDTM_X32(r, ta) \
    asm volatile( \
        "tcgen05.ld.sync.aligned.32x32b.x32.b32 " \
        "{%0, %1, %2, %3, %4, %5, %6, %7, " \
        " %8, %9, %10, %11, %12, %13, %14, %15, " \
        " %16, %17, %18, %19, %20, %21, %22, %23, " \
        " %24, %25, %26, %27, %28, %29, %30, %31}, [%32];" \
        : "=r"((r)[0]),  "=r"((r)[1]),  "=r"((r)[2]),  "=r"((r)[3]), \
          "=r"((r)[4]),  "=r"((r)[5]),  "=r"((r)[6]),  "=r"((r)[7]), \
          "=r"((r)[8]),  "=r"((r)[9]),  "=r"((r)[10]), "=r"((r)[11]), \
          "=r"((r)[12]), "=r"((r)[13]), "=r"((r)[14]), "=r"((r)[15]), \
          "=r"((r)[16]), "=r"((r)[17]), "=r"((r)[18]), "=r"((r)[19]), \
          "=r"((r)[20]), "=r"((r)[21]), "=r"((r)[22]), "=r"((r)[23]), \
          "=r"((r)[24]), "=r"((r)[25]), "=r"((r)[26]), "=r"((r)[27]), \
          "=r"((r)[28]), "=r"((r)[29]), "=r"((r)[30]), "=r"((r)[31]) \
        : "r"(ta))

__device__ __forceinline__ uint64_t sdesc(uint32_t addr){
  const uint64_t base = (2ull << 61) | (1ull << 46) | (64ull << 32) | (1ull << 16);
  return base | ((uint64_t)(addr >> 4) & 0x3FFF);
}

__device__ __forceinline__ void mma_ss_f16(uint32_t d, uint64_t ad, uint64_t bd, uint32_t idesc, uint32_t en){
  asm volatile(
    "{\n\t.reg .pred p;\n\tsetp.ne.u32 p, %5, 0;\n\t"
    "tcgen05.mma.cta_group::1.kind::f16 [%0], %1, %2, %3, {%4, %4, %4, %4}, p;\n\t}"
    :: "r"(d), "l"(ad), "l"(bd), "r"(idesc), "r"(0u), "r"(en) : "memory");
}

// idesc: dtype F32, atype/btype BF16, M=128, N=128 (halves A-tile smem re-reads vs N=64)
#define IDESC_128x128 ((1u<<4) | (1u<<7) | (1u<<10) | ((128u/8u)<<17) | ((128u/16u)<<24))
#endif // HAS_TCGEN05

// ---------------- scratch (device globals; no allocations allowed) ----------------
#define SCRATCH_FLOATS (524288 + 2097152 + 262144 + 12*TC)
__device__ float g_scratch[SCRATCH_FLOATS];

// bf16 pool
#define WSZ (2048*2048)
#define BF_EXTRA (2*524288 + 4*262144 + 2*131072 + 2*262144)
__device__ __align__(16) __nv_bfloat16 g_bf16[4*TC + 8*WSZ + BF_EXTRA];

// chunked-scan scratch
#define SCAN_FLOATS (3*1024*4096 + 2*1024*2048 + 1024*64)
__device__ float g_scan[SCAN_FLOATS];

// ---------------- generalized tcgen05 split-bf16 GEMM (3 CTAs/SM, N=128 atoms) -----
#define GEMM_SMEM_ALLOC 66560   // 1024 + 65536

__global__ void __launch_bounds__(256, 3)
#if HAS_TCGEN05
__cluster_dims__(1, 1, 1)
#endif
gemm_tcg(
    const __nv_bfloat16* __restrict__ Ah, const __nv_bfloat16* __restrict__ Al, int lda,
    const __nv_bfloat16* __restrict__ Bh0, const __nv_bfloat16* __restrict__ Bl0,
    const __nv_bfloat16* __restrict__ Bh1, const __nv_bfloat16* __restrict__ Bl1,
    const __nv_bfloat16* __restrict__ Bh2, const __nv_bfloat16* __restrict__ Bl2, int ldb,
    float* C0, float* C1, float* C2, int ldc,
    int kchunks, int kslice, long long cslice, int acol0, int acolz)
{
  extern __shared__ __align__(1024) char smem[];
  int tid = threadIdx.x;
  int z = blockIdx.z;
  int m0 = blockIdx.y * 128, n0 = blockIdx.x * 128;

  const __nv_bfloat16 *Bh, *Bl;
  float* C;
  int akoff, bkoff;
  if (kslice > 0){
    Bh = Bh0; Bl = Bl0;
    C = C0 + (long long)z * cslice;
    akoff = acol0 + z * kslice;
    bkoff = z * kslice;
  } else {
    Bh = (z == 0) ? Bh0 : (z == 1) ? Bh1 : Bh2;
    Bl = (z == 0) ? Bl0 : (z == 1) ? Bl1 : Bl2;
    C  = (z == 0) ? C0  : (z == 1) ? C1  : C2;
    akoff = acol0 + z * acolz;
    bkoff = 0;
  }

#if HAS_TCGEN05
  uint32_t sb = smem_u32(smem);
  int wid = tid >> 5, lid = tid & 31;

  if (wid == 0) { T5_ALLOC(sb, 128); T5_RELINQ(); }
  if (tid == 0) { MBAR_INIT(sb + 8, 1); }
  __syncthreads();
  uint32_t tmem;
  asm volatile("ld.shared.b32 %0, [%1];" : "=r"(tmem) : "r"(sb));

  int smoff[4];
  int offA[4], offB[4];
  #pragma unroll
  for (int i = 0; i < 4; i++){
    int e = tid + (i << 8);
    int row = e >> 3, seg = e & 7;
    smoff[i] = SW128(row*128 + seg*16);
    offA[i] = (m0 + row)*lda + seg*8;
    offB[i] = (n0 + row)*ldb + seg*8;
  }

  uint4 pf[8];
  #pragma unroll
  for (int i = 0; i < 4; i++){
    pf[i]     = *(const uint4*)(Bh + offB[i] + bkoff);
    pf[4 + i] = *(const uint4*)(Bl + offB[i] + bkoff);
  }

  for (int c = 0; c < kchunks; c++){
    int k0 = c * 64;
    #pragma unroll
    for (int i = 0; i < 4; i++){
      *(uint4*)(smem + 1024 + 32768 + smoff[i]) = pf[i];
      *(uint4*)(smem + 1024 + 49152 + smoff[i]) = pf[4 + i];
    }
    #pragma unroll
    for (int i = 0; i < 4; i++){
      uint4 va = *(const uint4*)(Ah + offA[i] + akoff + k0);
      uint4 vb = *(const uint4*)(Al + offA[i] + akoff + k0);
      *(uint4*)(smem + 1024         + smoff[i]) = va;
      *(uint4*)(smem + 1024 + 16384 + smoff[i]) = vb;
    }
    FENCE_ASYNC();
    __syncthreads();

    if (c + 1 < kchunks){
      int k1 = (c + 1) * 64;
      #pragma unroll
      for (int i = 0; i < 4; i++){
        pf[i]     = *(const uint4*)(Bh + offB[i] + bkoff + k1);
        pf[4 + i] = *(const uint4*)(Bl + offB[i] + bkoff + k1);
      }
    }

    if (wid == 0 && elect1()){
      uint64_t dah = sdesc(sb + 1024);
      uint64_t dal = sdesc(sb + 1024 + 16384);
      uint64_t dbh = sdesc(sb + 1024 + 32768);
      uint64_t dbl = sdesc(sb + 1024 + 49152);
      #pragma unroll
      for (int ks = 0; ks < 4; ks++){
        uint64_t off = 2*ks;
        uint32_t en0 = (c | ks) ? 1u : 0u;
        mma_ss_f16(tmem, dah + off, dbh + off, IDESC_128x128, en0);
        mma_ss_f16(tmem, dal + off, dbh + off, IDESC_128x128, 1u);
        mma_ss_f16(tmem, dah + off, dbl + off, IDESC_128x128, 1u);
      }
      T5_COMMIT(sb + 8);
    }
    MBAR_WAIT(sb + 8, c & 1);
    __syncthreads();
  }

  T5_FENCE_AFTER();

  {
    int half = wid >> 2, wq = wid & 3;
    #pragma unroll
    for (int nb = 0; nb < 2; nb++){
      uint32_t rr[32];
      LDTM_X32(rr, tmem + half*64 + nb*32);
      T5_WAIT_LD();
      float4* cp = (float4*)(C + (size_t)(m0 + wq*32 + lid) * ldc + n0 + half*64 + nb*32);
      #pragma unroll
      for (int q = 0; q < 8; q++)
        cp[q] = make_float4(__uint_as_float(rr[4*q]),   __uint_as_float(rr[4*q+1]),
                            __uint_as_float(rr[4*q+2]), __uint_as_float(rr[4*q+3]));
    }
  }
  __syncthreads();
  if (tid == 0) { MBAR_INVAL(sb + 8); }
  __syncthreads();
  if (wid == 0) { T5_DEALLOC(tmem, 128); }

#else
  int K = kchunks * 64;
  for (int idx = tid; idx < 128*128; idx += 256){
    int mi = idx >> 7, ni = idx & 127;
    float s = 0.f;
    for (int k = 0; k < K; k++){
      float av = __bfloat162float(Ah[(size_t)(m0+mi)*lda + akoff + k]) +
                 __bfloat162float(Al[(size_t)(m0+mi)*lda + akoff + k]);
      float bv = __bfloat162float(Bh[(size_t)(n0+ni)*ldb + bkoff + k]) +
                 __bfloat162float(Bl[(size_t)(n0+ni)*ldb + bkoff + k]);
      s += av * bv;
    }
    C[(size_t)(m0+mi)*ldc + n0 + ni] = s;
  }
#endif
}

// ---------------- operand-prep kernels ----------------
__global__ void splitf(const float* __restrict__ s, __nv_bfloat16* __restrict__ hi,
                       __nv_bfloat16* __restrict__ lo, int n)
{
  int i = blockIdx.x*256 + threadIdx.x;
  if (i < n){
    float f = s[i];
    __nv_bfloat16 h = __float2bfloat16(f);
    hi[i] = h;
    lo[i] = __float2bfloat16(f - __bfloat162float(h));
  }
}

__global__ void __launch_bounds__(256) tsplit(
    const float* __restrict__ Wr, const float* __restrict__ Wk,
    const float* __restrict__ Wv, const float* __restrict__ Wo,
    __nv_bfloat16* __restrict__ out)
{
  const float* W = (blockIdx.z == 0) ? Wr : (blockIdx.z == 1) ? Wk : (blockIdx.z == 2) ? Wv : Wo;
  __nv_bfloat16* Th = out + (size_t)blockIdx.z * 2 * WSZ;
  __nv_bfloat16* Tl = Th + WSZ;
  __shared__ float s[32][33];
  int nb = blockIdx.x*32, kb = blockIdx.y*32;
  int tid = threadIdx.x;

  #pragma unroll
  for (int e = tid; e < 1024; e += 256){
    int rr = e >> 5, cc = e & 31;
    s[rr][cc] = W[(size_t)(kb+rr)*2048 + nb + cc];
  }
  __syncthreads();

  #pragma unroll
  for (int e = tid; e < 512; e += 256){
    int n = e >> 4, kp = (e & 15) << 1;
    float f0 = s[kp][n],   f1 = s[kp+1][n];
    __nv_bfloat16 h0 = __float2bfloat16(f0), h1 = __float2bfloat16(f1);
    __nv_bfloat162 hv; hv.x = h0; hv.y = h1;
    __nv_bfloat162 lv;
    lv.x = __float2bfloat16(f0 - __bfloat162float(h0));
    lv.y = __float2bfloat16(f1 - __bfloat162float(h1));
    size_t oi = ((size_t)(nb+n)*2048 + kb + kp) >> 1;
    ((__nv_bfloat162*)Th)[oi] = hv;
    ((__nv_bfloat162*)Tl)[oi] = lv;
  }
}

__global__ void build_bcatT(const float* __restrict__ w1, const float* __restrict__ a1,
                            const float* __restrict__ v1,
                            __nv_bfloat16* __restrict__ Th, __nv_bfloat16* __restrict__ Tl)
{
  int i = blockIdx.x*256 + threadIdx.x;
  if (i >= 256*2048) return;
  int n = i >> 11, k = i & 2047;
  float f;
  if      (n <  96) f = w1[k*96 + n];
  else if (n < 192) f = a1[k*96 + n - 96];
  else              f = v1[k*64 + n - 192];
  __nv_bfloat16 h = __float2bfloat16(f);
  Th[i] = h;
  Tl[i] = __float2bfloat16(f - __bfloat162float(h));
}

__global__ void build_m2T(const float* __restrict__ w2, const float* __restrict__ a2,
                          const float* __restrict__ v2,
                          __nv_bfloat16* __restrict__ w2Th, __nv_bfloat16* __restrict__ w2Tl,
                          __nv_bfloat16* __restrict__ a2Th, __nv_bfloat16* __restrict__ a2Tl,
                          __nv_bfloat16* __restrict__ v2Th, __nv_bfloat16* __restrict__ v2Tl)
{
  int z = blockIdx.z;
  int ldk = (z == 2) ? 64 : 128;
  int Kz  = (z == 2) ? 64 : 96;
  int nel = 2048 * ldk;
  int i = blockIdx.x*256 + threadIdx.x;
  if (i >= nel) return;
  int kp = i & (ldk - 1), n = i / ldk;
  const float* M = (z == 0) ? w2 : (z == 1) ? a2 : v2;
  float f = (kp < Kz) ? M[(size_t)kp*2048 + n] : 0.f;
  __nv_bfloat16 h = __float2bfloat16(f);
  __nv_bfloat16* Th = (z == 0) ? w2Th : (z == 1) ? a2Th : v2Th;
  __nv_bfloat16* Tl = (z == 0) ? w2Tl : (z == 1) ? a2Tl : v2Tl;
  Th[i] = h;
  Tl[i] = __float2bfloat16(f - __bfloat162float(h));
}

__global__ void reduce_hcat(const float* __restrict__ part,
                            __nv_bfloat16* __restrict__ hch, __nv_bfloat16* __restrict__ hcl)
{
  int i = blockIdx.x*256 + threadIdx.x;
  if (i >= 1024*256) return;
  float s = 0.f;
  #pragma unroll
  for (int z = 0; z < 8; z++) s += part[(size_t)z*1024*256 + i];
  int col = i & 255;
  if (col < 96) s = tanhf(s);
  __nv_bfloat16 h = __float2bfloat16(s);
  hch[i] = h;
  hcl[i] = __float2bfloat16(s - __bfloat162float(h));
}

// sum the two Wo split-K partials; also copy v_first into out[TC..2TC)
__global__ void reduce_out(const float* __restrict__ p0, const float* __restrict__ vf,
                           float* __restrict__ out, int copy_vf)
{
  int i = blockIdx.x*256 + threadIdx.x;
  if (i < TC){
    out[i] = p0[i] + p0[TC + i];
    if (copy_vf) out[TC + i] = vf[i];
  }
}

// ---------------- elementwise prep (256 threads = 4 heads, shfl reductions) --------
__device__ __forceinline__ float sigmoidf_(float x){ return 1.f/(1.f + expf(-x)); }

__global__ void __launch_bounds__(256) prep_kernel(
    float* __restrict__ k, float* __restrict__ v,
    const float* __restrict__ gw, const float* __restrict__ ga, const float* __restrict__ gv,
    const float* __restrict__ v_first, const float* __restrict__ mask,
    const float* __restrict__ w0, const float* __restrict__ a0, const float* __restrict__ v0,
    const float* __restrict__ k_k, const float* __restrict__ k_a,
    float* __restrict__ dec, float* __restrict__ asc, float* __restrict__ bsc,
    float* __restrict__ ksc, float* __restrict__ vsc)
{
  int t  = blockIdx.x >> 3;
  int hq = blockIdx.x & 7;
  int tid = threadIdx.x;
  int c  = (hq << 8) | tid;
  int idx = t*Cc + c;

  float kr  = k[idx];
  float kkv = kr * k_k[c];

  float sq = kkv*kkv;
  #pragma unroll
  for (int o = 16; o > 0; o >>= 1) sq += __shfl_xor_sync(0xffffffffu, sq, o);
  __shared__ float hs[8];
  if ((tid & 31) == 0) hs[tid >> 5] = sq;
  __syncthreads();
  int g = tid >> 6;
  float tot = hs[2*g] + hs[2*g + 1];
  float kkn = kkv / fmaxf(sqrtf(tot), 1e-12f);

  float av = sigmoidf_(a0[c] + ga[idx]);
  float m  = mask[t];

  float y  = w0[c] + gw[idx];
  float z  = -y;
  float sp = (z > 20.f) ? z : log1pf(expf(z));
  float w  = -sp - 0.6f;
  float d  = expf(-expf(w));
  d = d*m + (1.f - m);

  float vr = v[idx];
  float sv = sigmoidf_(v0[c] + gv[idx]);
  float vm = fmaf(v_first[idx] - vr, sv, vr);

  float ku = kr * fmaf(av - 1.f, k_a[c], 1.f);

  k[idx]   = ku;
  v[idx]   = vm;
  dec[idx] = d;
  ksc[idx] = ku * m;
  vsc[idx] = vm * m;
  asc[idx] = -kkn * m;
  bsc[idx] = kkn * av * m;
}

// ================= chunked RWKV-7 scan (WY/UT-transform) =================
#define OGAM 0
#define OAH  2145
#define OBB  4225
#define OKB  6305
#define ORH  8385
#define OVS  10465
#define OZV  12545
#define OT1  14625
#define OT2  15649
#define OLB  16673
#define OLK  17697
#define S1_SMEM_FLOATS 18721   // 74884 bytes -> 3 blocks/SM

__global__ void __launch_bounds__(256, 3) scan_stage1(
    const float* __restrict__ dec, const float* __restrict__ r,
    const float* __restrict__ kq, const float* __restrict__ vq,
    const float* __restrict__ aq, const float* __restrict__ bq,
    float* __restrict__ U, float* __restrict__ F,
    float* __restrict__ RP, float* __restrict__ OL, float* __restrict__ GL)
{
  extern __shared__ float sm[];
  float* GAM = sm + OGAM;
  float* AH  = sm + OAH;
  float* BB  = sm + OBB;
  float* KB  = sm + OKB;
  float* RH  = sm + ORH;
  float* VS  = sm + OVS;
  float* ZV  = sm + OZV;
  float* T1  = sm + OT1;
  float* T2  = sm + OT2;
  float* LB  = sm + OLB;
  float* LK  = sm + OLK;

  int p = blockIdx.x;
  int h = p >> 5, c = p & 31;
  int t0 = c * SL, hb = h << 6;
  int tid = threadIdx.x;

  for (int e = tid; e < SL*64; e += 256){
    int t = e >> 6, j = e & 63;
    AH[t*65+j] = dec[(size_t)(t0+t)*Cc + hb + j];
  }
  __syncthreads();
  if (tid < 64){
    float g = 1.f;
    GAM[0*65 + tid] = 1.f;
    #pragma unroll
    for (int t = 0; t < SL; t++){
      g *= AH[t*65 + tid];
      GAM[(t+1)*65 + tid] = g;
    }
  }
  __syncthreads();

  for (int e = tid; e < SL*64; e += 256){
    int t = e >> 6, j = e & 63;
    size_t gi = (size_t)(t0+t)*Cc + hb + j;
    float gp = GAM[t*65 + j];
    float gt = GAM[(t+1)*65 + j];
    AH[t*65+j] = aq[gi] * gp;
    BB[t*65+j] = bq[gi] / gt;
    KB[t*65+j] = kq[gi] / gt;
    RH[t*65+j] = r[gi] * gt;
    VS[t*65+j] = vq[gi];
  }
  __syncthreads();

  {
    int t0i = (tid >> 4) << 1;
    int s0i = (tid & 15) << 1;
    float d1[4]={0,0,0,0}, d2[4]={0,0,0,0}, d3[4]={0,0,0,0}, d4[4]={0,0,0,0};
    for (int j = 0; j < 64; j++){
      float a0 = AH[t0i*65+j],     a1 = AH[(t0i+1)*65+j];
      float r0 = RH[t0i*65+j],     r1 = RH[(t0i+1)*65+j];
      float b0 = BB[s0i*65+j],     b1 = BB[(s0i+1)*65+j];
      float k0 = KB[s0i*65+j],     k1 = KB[(s0i+1)*65+j];
      d1[0]=fmaf(b0,a0,d1[0]); d1[1]=fmaf(b1,a0,d1[1]); d1[2]=fmaf(b0,a1,d1[2]); d1[3]=fmaf(b1,a1,d1[3]);
      d2[0]=fmaf(k0,a0,d2[0]); d2[1]=fmaf(k1,a0,d2[1]); d2[2]=fmaf(k0,a1,d2[2]); d2[3]=fmaf(k1,a1,d2[3]);
      d3[0]=fmaf(b0,r0,d3[0]); d3[1]=fmaf(b1,r0,d3[1]); d3[2]=fmaf(b0,r1,d3[2]); d3[3]=fmaf(b1,r1,d3[3]);
      d4[0]=fmaf(k0,r0,d4[0]); d4[1]=fmaf(k1,r0,d4[1]); d4[2]=fmaf(k0,r1,d4[2]); d4[3]=fmaf(k1,r1,d4[3]);
    }
    #pragma unroll
    for (int q = 0; q < 4; q++){
      int t = t0i + (q >> 1), s = s0i + (q & 1);
      T1[t*SL+s] = (s <  t) ? d1[q] : 0.f;
      T2[t*SL+s] = (s <  t) ? d2[q] : 0.f;
      LB[t*SL+s] = (s <= t) ? d3[q] : 0.f;
      LK[t*SL+s] = (s <= t) ? d4[q] : 0.f;
    }
  }
  __syncthreads();

  {
    int t = tid >> 3, j0 = (tid & 7) << 3;
    float zz[8] = {0,0,0,0,0,0,0,0};
    for (int s = 0; s < SL; s++){
      float t2 = T2[t*SL+s];
      #pragma unroll
      for (int q = 0; q < 8; q++) zz[q] = fmaf(t2, VS[s*65+j0+q], zz[q]);
    }
    #pragma unroll
    for (int q = 0; q < 8; q++) ZV[t*65+j0+q] = zz[q];
  }
  __syncthreads();

  if (tid < 128){
    int j = tid & 63;
    float* M = (tid < 64) ? AH : ZV;
    for (int t = 1; t < SL; t++){
      float acc = M[t*65+j];
      for (int s = 0; s < t; s++) acc += T1[t*SL+s] * M[s*65+j];
      M[t*65+j] = acc;
    }
  }
  __syncthreads();

  {
    int t = tid >> 3, j0 = (tid & 7) << 3;
    float rp[8], ol[8];
    #pragma unroll
    for (int q = 0; q < 8; q++){ rp[q] = RH[t*65+j0+q]; ol[q] = 0.f; }
    for (int s = 0; s <= t; s++){
      float lb = LB[t*SL+s], lk = LK[t*SL+s];
      #pragma unroll
      for (int q = 0; q < 8; q++){
        rp[q] = fmaf(lb, AH[s*65+j0+q], rp[q]);
        ol[q] = fmaf(lb, ZV[s*65+j0+q], fmaf(lk, VS[s*65+j0+q], ol[q]));
      }
    }
    #pragma unroll
    for (int q = 0; q < 8; q++){
      RP[(size_t)p*2048 + t*64 + j0 + q] = rp[q];
      OL[(size_t)p*2048 + t*64 + j0 + q] = ol[q];
    }
  }

  {
    int i0 = (tid >> 4) << 2;
    int j0 = (tid & 15) << 2;
    float u[16], f[16];
    #pragma unroll
    for (int q = 0; q < 16; q++){ u[q] = 0.f; f[q] = 0.f; }
    for (int t = 0; t < SL; t++){
      float ws[4], zv[4], vs[4], bb[4], kb[4];
      #pragma unroll
      for (int ii = 0; ii < 4; ii++){
        ws[ii] = AH[t*65+i0+ii];
        zv[ii] = ZV[t*65+i0+ii];
        vs[ii] = VS[t*65+i0+ii];
      }
      #pragma unroll
      for (int jj = 0; jj < 4; jj++){
        bb[jj] = BB[t*65+j0+jj];
        kb[jj] = KB[t*65+j0+jj];
      }
      #pragma unroll
      for (int ii = 0; ii < 4; ii++)
        #pragma unroll
        for (int jj = 0; jj < 4; jj++){
          u[ii*4+jj] = fmaf(ws[ii], bb[jj], u[ii*4+jj]);
          f[ii*4+jj] = fmaf(zv[ii], bb[jj], fmaf(vs[ii], kb[jj], f[ii*4+jj]));
        }
    }
    #pragma unroll
    for (int ii = 0; ii < 4; ii++)
      #pragma unroll
      for (int jj = 0; jj < 4; jj++){
        float glj = GAM[SL*65 + j0 + jj];
        U[(size_t)p*4096 + (i0+ii)*64 + j0 + jj] = u[ii*4+jj] * glj;
        F[(size_t)p*4096 + (i0+ii)*64 + j0 + jj] = f[ii*4+jj] * glj;
      }
  }
  if (tid < 64) GL[(size_t)p*64 + tid] = GAM[SL*65 + tid];
}

// stage2 parallelized over (head, 8-row blocks)
__global__ void __launch_bounds__(128) scan_stage2(
    const float* __restrict__ U, const float* __restrict__ F,
    const float* __restrict__ GL, float* __restrict__ S0out)
{
  int h  = blockIdx.x >> 3;
  int rb = blockIdx.x & 7;
  int i0 = rb * 8;
  int tid = threadIdx.x;
  int il = tid >> 4;
  int j0 = (tid & 15) * 4;
  __shared__ float Ss[8][65];
  __shared__ float Us[64*64];
  for (int e = tid; e < 8*65; e += 128) (&Ss[0][0])[e] = 0.f;
  __syncthreads();

  for (int c = 0; c < NCH; c++){
    size_t p = (size_t)(h*NCH + c);
    const float* Up = U + p*4096;
    const float* Fp = F + p*4096;
    const float* Gp = GL + p*64;
    float* S0p = S0out + p*4096;
    #pragma unroll
    for (int q = 0; q < 4; q++)
      S0p[(i0+il)*64 + j0 + q] = Ss[il][j0+q];
    for (int e = tid; e < 4096; e += 128) Us[e] = Up[e];
    __syncthreads();
    float acc[4];
    #pragma unroll
    for (int q = 0; q < 4; q++)
      acc[q] = Ss[il][j0+q] * Gp[j0+q] + Fp[(i0+il)*64 + j0 + q];
    for (int k = 0; k < 64; k++){
      float sik = Ss[il][k];
      #pragma unroll
      for (int q = 0; q < 4; q++) acc[q] = fmaf(sik, Us[k*64+j0+q], acc[q]);
    }
    __syncthreads();
    #pragma unroll
    for (int q = 0; q < 4; q++) Ss[il][j0+q] = acc[q];
    __syncthreads();
  }
}

// stage3 fused with residual; register-blocked 4t x 2i matmul tiles
__global__ void __launch_bounds__(256) scan_stage3(
    const float* __restrict__ RP, const float* __restrict__ OL,
    const float* __restrict__ S0,
    const float* __restrict__ r, const float* __restrict__ k,
    const float* __restrict__ v, const float* __restrict__ r_k,
    __nv_bfloat16* __restrict__ oh, __nv_bfloat16* __restrict__ ol)
{
  int p = blockIdx.x;
  int h = p >> 5, c = p & 31;
  int t0 = c * SL, hb = h << 6;
  int tid = threadIdx.x;
  __shared__ float S0s[64*65];
  __shared__ float RPs[2048];
  __shared__ float rsum[SL][2];
  for (int e = tid; e < 4096; e += 256) S0s[(e>>6)*65 + (e&63)] = S0[(size_t)p*4096 + e];
  for (int e = tid; e < 2048; e += 256) RPs[e] = RP[(size_t)p*2048 + e];
  __syncthreads();

  for (int e = tid; e < 2048; e += 256){
    int t = e >> 6, i = e & 63;
    size_t gi = (size_t)(t0+t)*Cc + hb + i;
    float pr = r[gi]*k[gi]*r_k[hb + i];
    #pragma unroll
    for (int o = 16; o > 0; o >>= 1) pr += __shfl_xor_sync(0xffffffffu, pr, o);
    if ((e & 31) == 0) rsum[t][(i >> 5) & 1] = pr;
  }
  __syncthreads();

  {
    int tg = tid >> 5;
    int tb = tg * 4;
    int ii = tid & 31;
    int i0 = ii * 2;
    float acc[4][2];
    #pragma unroll
    for (int q = 0; q < 4; q++)
      #pragma unroll
      for (int pq = 0; pq < 2; pq++)
        acc[q][pq] = OL[(size_t)p*2048 + (tb+q)*64 + i0 + pq];
    for (int j = 0; j < 64; j++){
      float s0a = S0s[i0*65 + j];
      float s0b = S0s[(i0+1)*65 + j];
      #pragma unroll
      for (int q = 0; q < 4; q++){
        float rp = RPs[(tb+q)*64 + j];
        acc[q][0] = fmaf(rp, s0a, acc[q][0]);
        acc[q][1] = fmaf(rp, s0b, acc[q][1]);
      }
    }
    #pragma unroll
    for (int q = 0; q < 4; q++){
      int t = tb + q;
      float rs = rsum[t][0] + rsum[t][1];
      #pragma unroll
      for (int pq = 0; pq < 2; pq++){
        size_t gi = (size_t)(t0+t)*Cc + hb + i0 + pq;
        float val = fmaf(rs, v[gi], acc[q][pq]);
        __nv_bfloat16 hh = __float2bfloat16(val);
        oh[gi] = hh;
        ol[gi] = __float2bfloat16(val - __bfloat162float(hh));
      }
    }
  }
}

// ---------------- host launcher ----------------
extern "C" void kernel_launch(void* const* d_in, const int* in_sizes, int n_in,
                              void* d_out, int out_size)
{
  const float* x        = (const float*)d_in[0];
  const float* v_first  = (const float*)d_in[1];
  const float* mask     = (const float*)d_in[2];
  const float* w0       = (const float*)d_in[3];
  const float* w1       = (const float*)d_in[4];
  const float* w2       = (const float*)d_in[5];
  const float* a0       = (const float*)d_in[6];
  const float* a1       = (const float*)d_in[7];
  const float* a2       = (const float*)d_in[8];
  const float* v0       = (const float*)d_in[9];
  const float* v1       = (const float*)d_in[10];
  const float* v2       = (const float*)d_in[11];
  const float* k_k      = (const float*)d_in[12];
  const float* k_a      = (const float*)d_in[13];
  const float* r_k      = (const float*)d_in[14];
  const float* Wr       = (const float*)d_in[15];
  const float* Wk       = (const float*)d_in[16];
  const float* Wv       = (const float*)d_in[17];
  const float* Wo       = (const float*)d_in[18];
  float* outf = (float*)d_out;

  float* S = nullptr;
  cudaGetSymbolAddress((void**)&S, g_scratch);
  __nv_bfloat16* BF = nullptr;
  cudaGetSymbolAddress((void**)&BF, g_bf16);
  float* SC = nullptr;
  cudaGetSymbolAddress((void**)&SC, g_scan);

  float* bcat = S;
  float* part = bcat + 524288;
  float* hcat = part + 2097152;
  float* gw   = hcat + 262144;
  float* ga   = gw  + TC;
  float* gv   = ga  + TC;
  float* r    = gv  + TC;
  float* k    = r   + TC;
  float* v    = k   + TC;
  float* dec  = v   + TC;
  float* asc  = dec + TC;
  float* bsc  = asc + TC;
  float* ksc  = bsc + TC;
  float* vsc  = ksc + TC;
  float* wop  = gw;            // Wo split-K(2) partials (2*TC) reuse gw/ga (dead after prep)

  __nv_bfloat16* xh = BF;
  __nv_bfloat16* xl = xh + TC;
  __nv_bfloat16* oh = xl + TC;
  __nv_bfloat16* ol = oh + TC;
  __nv_bfloat16* Wt = ol + TC;
  __nv_bfloat16* Wrh = Wt + 0*WSZ, *Wrl = Wt + 1*WSZ;
  __nv_bfloat16* Wkh = Wt + 2*WSZ, *Wkl = Wt + 3*WSZ;
  __nv_bfloat16* Wvh = Wt + 4*WSZ, *Wvl = Wt + 5*WSZ;
  __nv_bfloat16* Woh = Wt + 6*WSZ, *Wol = Wt + 7*WSZ;
  __nv_bfloat16* ext  = Wt + 8*WSZ;
  __nv_bfloat16* bcTh = ext;
  __nv_bfloat16* bcTl = bcTh + 524288;
  __nv_bfloat16* w2Th = bcTl + 524288;
  __nv_bfloat16* w2Tl = w2Th + 262144;
  __nv_bfloat16* a2Th = w2Tl + 262144;
  __nv_bfloat16* a2Tl = a2Th + 262144;
  __nv_bfloat16* v2Th = a2Tl + 262144;
  __nv_bfloat16* v2Tl = v2Th + 131072;
  __nv_bfloat16* hch  = v2Tl + 131072;
  __nv_bfloat16* hcl  = hch + 262144;

  float* scS0 = SC;
  float* scU  = scS0 + 1024*4096;
  float* scF  = scU  + 1024*4096;
  float* scRP = scF  + 1024*4096;
  float* scOL = scRP + 1024*2048;
  float* scGL = scOL + 1024*2048;

  cudaFuncSetAttribute(gemm_tcg, cudaFuncAttributeMaxDynamicSharedMemorySize, GEMM_SMEM_ALLOC);
  cudaFuncSetAttribute(scan_stage1, cudaFuncAttributeMaxDynamicSharedMemorySize, S1_SMEM_FLOATS*4);

  // 0) operand prep — rkv GEMM in launch slot 4 (ncu profile slot)
  splitf<<<TC/256, 256>>>(x, xh, xl, TC);                                     // 1
  tsplit<<<dim3(64,64,4), 256>>>(Wr, Wk, Wv, Wo, Wt);                         // 2
  build_bcatT<<<(256*2048)/256, 256>>>(w1, a1, v1, bcTh, bcTl);               // 3

  // 1) big GEMMs: r,k,v = x @ {Wr,Wk,Wv}                                      // 4 (profiled)
  {
    dim3 grid(16, 8, 3);
    gemm_tcg<<<grid, 256, GEMM_SMEM_ALLOC>>>(
        xh, xl, 2048,
        Wrh, Wrl, Wkh, Wkl, Wvh, Wvl, 2048,
        r, k, v, 2048,
        32, 0, 0LL, 0, 0);
  }

  build_m2T<<<dim3(1024,1,3), 256>>>(w2, a2, v2, w2Th, w2Tl, a2Th, a2Tl, v2Th, v2Tl);

  // 2) thin GEMM (split-K 8)
  {
    dim3 grid(2, 8, 8);
    gemm_tcg<<<grid, 256, GEMM_SMEM_ALLOC>>>(
        xh, xl, 2048,
        bcTh, bcTl, bcTh, bcTl, bcTh, bcTl, 2048,
        part, part, part, 256,
        4, 256, 262144LL, 0, 0);
  }
  reduce_hcat<<<1024, 256>>>(part, hch, hcl);

  // 3) mid GEMMs
  {
    dim3 gwa(16, 8, 2);
    gemm_tcg<<<gwa, 256, GEMM_SMEM_ALLOC>>>(
        hch, hcl, 256,
        w2Th, w2Tl, a2Th, a2Tl, a2Th, a2Tl, 128,
        gw, ga, ga, 2048,
        2, 0, 0LL, 0, 96);
    dim3 gv_(16, 8, 1);
    gemm_tcg<<<gv_, 256, GEMM_SMEM_ALLOC>>>(
        hch, hcl, 256,
        v2Th, v2Tl, v2Th, v2Tl, v2Th, v2Tl, 64,
        gv, gv, gv, 2048,
        1, 0, 0LL, 192, 0);
  }

  // 4) elementwise prep
  prep_kernel<<<Tt*8, 256>>>(k, v, gw, ga, gv, v_first, mask,
                             w0, a0, v0, k_k, k_a,
                             dec, asc, bsc, ksc, vsc);

  // 5) chunked scan
  scan_stage1<<<Hh*NCH, 256, S1_SMEM_FLOATS*4>>>(dec, r, ksc, vsc, asc, bsc,
                                                 scU, scF, scRP, scOL, scGL);
  scan_stage2<<<Hh*8, 128>>>(scU, scF, scGL, scS0);
  scan_stage3<<<Hh*NCH, 256>>>(scRP, scOL, scS0, r, k, v, r_k, oh, ol);

  // 6) final GEMM: out = o @ Wo via split-K(2) + reduce (+ v_first copy fused)
  {
    dim3 grid(16, 8, 2);
    gemm_tcg<<<grid, 256, GEMM_SMEM_ALLOC>>>(
        oh, ol, 2048,
        Woh, Wol, Woh, Wol, Woh, Wol, 2048,
        wop, wop, wop, 2048,
        16, /*kslice=*/1024, /*cslice=*/(long long)TC, 0, 0);
  }
  reduce_out<<<TC/256, 256>>>(wop, v_first, outf, (out_size >= 2*TC) ? 1 : 0);
}